// round 13
// baseline (speedup 1.0000x reference)
#include <cuda_runtime.h>
#include <cuda_bf16.h>
#include <math.h>
#include <stdint.h>

// Problem constants
constexpr int VOCAB = 10000;
constexpr int EMB   = 1500;
constexpr int HID   = 1500;
constexpr int T     = 35;
constexpr int B     = 64;
constexpr float FORGET_BIAS = 1.0f;

// Recurrence partitioning: 6000 gate cols = 125 blocks * 48 cols (12 hidden units * 4 gates)
constexpr int NBLK = 125;
constexpr int CPB  = 48;   // cols per block
constexpr int HROW = 1536; // padded row stride for h buffers (multiple of 64)
constexpr int KA   = 1504; // padded activation row stride

// ---------------- static device scratch ----------------
__device__ __align__(128) float g_xz0[(size_t)T * B * 6000];       // interleaved cols
__device__ __align__(128) float g_logits[(size_t)T * B * VOCAB];
__device__ __align__(128) float g_c0[B * HID];
__device__ __align__(128) float g_c1[B * HID];
__device__ __align__(128) float g_nll[T * B];
__device__ __align__(128) float g_b0i[6000];
__device__ __align__(128) float g_b1i[6000];
__device__ __align__(128) __nv_bfloat16 g_inputs[(size_t)T * B * KA];      // padded rows
__device__ __align__(128) __nv_bfloat16 g_W0i[(size_t)(EMB + HID) * 6000]; // gate-interleaved
__device__ __align__(128) __nv_bfloat16 g_W1i[(size_t)2 * HID * 6000];     // gate-interleaved
__device__ __align__(128) __nv_bfloat16 g_swb[(size_t)HID * VOCAB];
__device__ __align__(128) __nv_bfloat16 g_h0[2][B * HROW];  // ping-pong h0
__device__ __align__(128) __nv_bfloat16 g_h1[2][B * HROW];  // ping-pong h1
__device__ __align__(128) __nv_bfloat16 g_out[(size_t)T * B * KA];         // padded rows
__device__ unsigned g_barCount;
__device__ unsigned g_barGen;

__device__ __forceinline__ float sigmoidf_(float x) {
    return 1.0f / (1.0f + expf(-x));
}

// ---------------- fused prep: misc init + ALL weight conversions ----------------
__global__ void prep_all_kernel(const float* __restrict__ b0, const float* __restrict__ b1,
                                const float* __restrict__ W0, const float* __restrict__ W1,
                                const float* __restrict__ sw) {
    constexpr int N0 = (EMB + HID) * 1500;   // W0 (row, unit) pairs
    constexpr int N1 = 2 * HID * 1500;       // W1
    constexpr int N2 = HID * VOCAB / 2;      // sw float2 pairs
    const int i0 = blockIdx.x * blockDim.x + threadIdx.x;

    // misc init (covered by the first grid sweep; grid is >= all these ranges)
    if (i0 == 0) { g_barCount = 0u; g_barGen = 0u; }
    const __nv_bfloat16 z = __float2bfloat16(0.0f);
    if (i0 < B * HROW) {
        g_h0[0][i0] = z; g_h0[1][i0] = z;
        g_h1[0][i0] = z; g_h1[1][i0] = z;
    }
    if (i0 < B * HID) { g_c0[i0] = 0.0f; g_c1[i0] = 0.0f; }
    if (i0 < T * B * 4) {
        const int r = i0 >> 2, c = i0 & 3;
        g_out[(size_t)r * KA + 1500 + c] = z;
    }
    if (i0 < 6000) {
        const int g = i0 / 1500, j = i0 % 1500;
        g_b0i[4 * j + g] = b0[i0];
        g_b1i[4 * j + g] = b1[i0];
    }

    long long i = i0;
    const long long stride = gridDim.x * (long long)blockDim.x;
    for (; i < (long long)N0 + N1 + N2; i += stride) {
        if (i < N0) {
            const int r = (int)(i / 1500), j = (int)(i % 1500);
            const float* s = W0 + (size_t)r * 6000;
            const __nv_bfloat162 p0 = __floats2bfloat162_rn(s[j], s[1500 + j]);
            const __nv_bfloat162 p1 = __floats2bfloat162_rn(s[3000 + j], s[4500 + j]);
            uint2 pk;
            pk.x = *reinterpret_cast<const uint32_t*>(&p0);
            pk.y = *reinterpret_cast<const uint32_t*>(&p1);
            *reinterpret_cast<uint2*>(g_W0i + (size_t)r * 6000 + 4 * j) = pk;
        } else if (i < (long long)N0 + N1) {
            const int ii = (int)(i - N0);
            const int r = ii / 1500, j = ii % 1500;
            const float* s = W1 + (size_t)r * 6000;
            const __nv_bfloat162 p0 = __floats2bfloat162_rn(s[j], s[1500 + j]);
            const __nv_bfloat162 p1 = __floats2bfloat162_rn(s[3000 + j], s[4500 + j]);
            uint2 pk;
            pk.x = *reinterpret_cast<const uint32_t*>(&p0);
            pk.y = *reinterpret_cast<const uint32_t*>(&p1);
            *reinterpret_cast<uint2*>(g_W1i + (size_t)r * 6000 + 4 * j) = pk;
        } else {
            const int ii = (int)(i - N0 - N1);
            const float2 v = reinterpret_cast<const float2*>(sw)[ii];
            reinterpret_cast<__nv_bfloat162*>(g_swb)[ii] = __floats2bfloat162_rn(v.x, v.y);
        }
    }
}

// embedding gather into padded rows (pad cols zeroed)
__global__ void embed_kernel(const int* __restrict__ x, const float* __restrict__ emb) {
    const int row = blockIdx.x;
    const int tok = x[row];
    const float2* src = reinterpret_cast<const float2*>(emb + (size_t)tok * EMB);
    __nv_bfloat162* dst = reinterpret_cast<__nv_bfloat162*>(g_inputs + (size_t)row * KA);
    for (int i = threadIdx.x; i < KA / 2; i += blockDim.x) {
        if (i < EMB / 2) {
            float2 v = src[i];
            dst[i] = __floats2bfloat162_rn(v.x, v.y);
        } else {
            dst[i] = __floats2bfloat162_rn(0.0f, 0.0f);
        }
    }
}

// ---------------- pipelined bf16 tensor-core GEMM (big batched GEMMs) ----------------
constexpr int GP_PIPE = 3;
constexpr int GP_SMEM = GP_PIPE * (128 * 40 + 32 * 136) * 2;  // 56832 bytes

__global__ void __launch_bounds__(256, 2)
gemm_pipe(const __nv_bfloat16* __restrict__ A, const __nv_bfloat16* __restrict__ Bm,
          float* __restrict__ C, int M, int N, int K,
          int lda, int ldb, int ldc)
{
    extern __shared__ char dynsmem[];
    typedef __nv_bfloat16 (*AsT)[128][40];
    typedef __nv_bfloat16 (*BsT)[32][136];
    AsT As = reinterpret_cast<AsT>(dynsmem);
    BsT Bs = reinterpret_cast<BsT>(dynsmem + GP_PIPE * 128 * 40 * 2);

    const int tid = threadIdx.x;
    const int lane = tid & 31;
    const int warp = tid >> 5;
    const int wm = warp >> 2;
    const int wn = warp & 3;
    const int row0 = blockIdx.y * 128;
    const int col0 = blockIdx.x * 128;
    const int KITER = (K + 31) / 32;

    const int arow = tid >> 2;
    const int acol = (tid & 3) * 8;
    const int brow = tid >> 4;
    const int bcol = (tid & 15) * 8;

    const int lrow = ((lane >> 3) & 1) * 8 + (lane & 7);
    const int lcol = (lane >> 4) * 8;

    float acc[4][4][4];
#pragma unroll
    for (int mt = 0; mt < 4; mt++)
#pragma unroll
        for (int nt = 0; nt < 4; nt++)
#pragma unroll
            for (int r = 0; r < 4; r++) acc[mt][nt][r] = 0.0f;

    auto issue = [&](int it) {
        const int k0 = it * 32;
        const int sb = it % GP_PIPE;
#pragma unroll
        for (int h = 0; h < 2; h++) {
            const int r = arow + h * 64;
            const int gr = row0 + r;
            const int grc = min(gr, M - 1);
            const int bytes = (gr < M) ? 16 : 0;
            uint32_t da = (uint32_t)__cvta_generic_to_shared(&As[sb][r][acol]);
            const void* sa = A + (size_t)grc * lda + k0 + acol;
            asm volatile("cp.async.cg.shared.global [%0], [%1], 16, %2;"
                         :: "r"(da), "l"(sa), "r"(bytes));
        }
#pragma unroll
        for (int h = 0; h < 2; h++) {
            const int r = brow + h * 16;
            const int gk = k0 + r;
            const int gc = col0 + bcol;
            const int bytes = (gk < K && gc < N) ? 16 : 0;
            const int gkc = min(gk, K - 1);
            const int gcc = min(gc, N - 8);
            uint32_t db = (uint32_t)__cvta_generic_to_shared(&Bs[sb][r][bcol]);
            const void* sbp = Bm + (size_t)gkc * ldb + gcc;
            asm volatile("cp.async.cg.shared.global [%0], [%1], 16, %2;"
                         :: "r"(db), "l"(sbp), "r"(bytes));
        }
    };

    issue(0);
    asm volatile("cp.async.commit_group;");
    issue(1);
    asm volatile("cp.async.commit_group;");

#pragma unroll 1
    for (int it = 0; it < KITER; it++) {
        asm volatile("cp.async.wait_group 1;");
        __syncthreads();
        if (it + 2 < KITER) issue(it + 2);
        asm volatile("cp.async.commit_group;");

        const int b = it % GP_PIPE;
#pragma unroll
        for (int ks = 0; ks < 32; ks += 16) {
            uint32_t ar[4][4];
            uint32_t br[2][4];
#pragma unroll
            for (int mt = 0; mt < 4; mt++) {
                uint32_t addr = (uint32_t)__cvta_generic_to_shared(
                    &As[b][wm * 64 + mt * 16 + lrow][ks + lcol]);
                asm volatile("ldmatrix.sync.aligned.m8n8.x4.shared.b16 {%0,%1,%2,%3}, [%4];"
                    : "=r"(ar[mt][0]), "=r"(ar[mt][1]), "=r"(ar[mt][2]), "=r"(ar[mt][3])
                    : "r"(addr));
            }
#pragma unroll
            for (int q = 0; q < 2; q++) {
                uint32_t addr = (uint32_t)__cvta_generic_to_shared(
                    &Bs[b][ks + lrow][wn * 32 + q * 16 + lcol]);
                asm volatile("ldmatrix.sync.aligned.m8n8.x4.trans.shared.b16 {%0,%1,%2,%3}, [%4];"
                    : "=r"(br[q][0]), "=r"(br[q][1]), "=r"(br[q][2]), "=r"(br[q][3])
                    : "r"(addr));
            }
#pragma unroll
            for (int mt = 0; mt < 4; mt++)
#pragma unroll
                for (int nt = 0; nt < 4; nt++) {
                    const int q = nt >> 1;
                    const int p = (nt & 1) * 2;
                    asm volatile(
                        "mma.sync.aligned.m16n8k16.row.col.f32.bf16.bf16.f32 "
                        "{%0,%1,%2,%3}, {%4,%5,%6,%7}, {%8,%9}, {%0,%1,%2,%3};"
                        : "+f"(acc[mt][nt][0]), "+f"(acc[mt][nt][1]),
                          "+f"(acc[mt][nt][2]), "+f"(acc[mt][nt][3])
                        : "r"(ar[mt][0]), "r"(ar[mt][1]), "r"(ar[mt][2]), "r"(ar[mt][3]),
                          "r"(br[q][p]), "r"(br[q][p + 1]));
                }
        }
    }

#pragma unroll
    for (int mt = 0; mt < 4; mt++) {
        const int r0 = row0 + wm * 64 + mt * 16 + (lane >> 2);
#pragma unroll
        for (int nt = 0; nt < 4; nt++) {
            const int c = col0 + wn * 32 + nt * 8 + (lane & 3) * 2;
            if (c < N) {
                if (r0 < M) {
                    C[(long long)r0 * ldc + c]     = acc[mt][nt][0];
                    C[(long long)r0 * ldc + c + 1] = acc[mt][nt][1];
                }
                if (r0 + 8 < M) {
                    C[(long long)(r0 + 8) * ldc + c]     = acc[mt][nt][2];
                    C[(long long)(r0 + 8) * ldc + c + 1] = acc[mt][nt][3];
                }
            }
        }
    }
}

// ---------------- lightweight grid barrier ----------------
__device__ __forceinline__ void grid_barrier(unsigned target) {
    __syncthreads();
    if (threadIdx.x == 0) {
        unsigned a;
        asm volatile("atom.add.release.gpu.u32 %0, [%1], %2;"
                     : "=r"(a) : "l"(&g_barCount), "r"(1u) : "memory");
        if (a == (unsigned)(NBLK - 1)) {
            g_barCount = 0u;
            asm volatile("st.release.gpu.u32 [%0], %1;" :: "l"(&g_barGen), "r"(target) : "memory");
        } else {
            unsigned g;
            do {
                asm volatile("ld.acquire.gpu.u32 %0, [%1];" : "=r"(g) : "l"(&g_barGen) : "memory");
            } while ((int)(g - target) < 0);
        }
    }
    __syncthreads();
}

// ---------------- persistent recurrence: merged phases + W0h persisted in smem ----------------
// Block's 48 W0h columns (1500x48 bf16 = 144 KB) are loaded into smem ONCE and
// reused all 35 steps, removing 144 KB/block/step of L2 traffic and the dual-B
// load in segment 1. Stride 48 (no pad): degree-2 ldsm conflicts, acceptable
// (smem ports are not the binder, R11).
// Phase t: seg1 (24 iters) A=h0(t): Wp(smem)->accA, W1a->accB. seg2 (24 iters)
// A=h1(t-1): W1b->accB. Epilogue: gates1(t), gates0(t+1). One barrier/phase.
constexpr int RC_PIPE = 3;
struct RcSmem {
    __nv_bfloat16 Wp[1536][48];           // 147456 B persistent W0h cols
    __nv_bfloat16 As[RC_PIPE][64][72];    // 27648 B
    __nv_bfloat16 Bs1[RC_PIPE][64][56];   // 21504 B
    float zs[64][52];                     // 13312 B
};
constexpr int RC_SMEM = sizeof(RcSmem);   // 209920 bytes

__global__ void __launch_bounds__(256, 1) recurrence_kernel() {
    extern __shared__ char dynsmem[];
    RcSmem* S = reinterpret_cast<RcSmem*>(dynsmem);

    const int tid = threadIdx.x;
    const int lane = tid & 31;
    const int warp = tid >> 5;
    const int kg = warp >> 1;        // 0..3  K-group
    const int wn = warp & 1;         // 0..1  N-half
    const int col0 = blockIdx.x * CPB;
    const int lrow = ((lane >> 3) & 1) * 8 + (lane & 7);
    const int lcol = (lane >> 4) * 8;
    const int x2row = lane & 15;

    const __nv_bfloat16* W0h = g_W0i + (size_t)EMB * 6000;

    // -------- load persistent W0h block columns into smem --------
    {
        // zero pad rows [1500, 1536)
        for (int slot = tid; slot < 36 * 6; slot += 256) {
            const int row = 1500 + slot / 6, v = slot % 6;
            *reinterpret_cast<uint4*>(&S->Wp[row][v * 8]) = make_uint4(0u, 0u, 0u, 0u);
        }
        for (int idx = tid; idx < 1500 * 6; idx += 256) {
            const int row = idx / 6, v = idx % 6;
            uint32_t d = (uint32_t)__cvta_generic_to_shared(&S->Wp[row][v * 8]);
            const void* s = W0h + (size_t)row * 6000 + col0 + v * 8;
            asm volatile("cp.async.cg.shared.global [%0], [%1], 16;" :: "r"(d), "l"(s));
        }
        asm volatile("cp.async.commit_group;");
        asm volatile("cp.async.wait_group 0;");
    }

    // -------- bootstrap: gates0(0) from xz0(0)+b0 (h(-1)=0, c=0) --------
#pragma unroll
    for (int i = 0; i < 3; i++) {
        const int ul = i * 256 + tid;
        const int bb = ul / 12;
        const int u  = ul % 12;
        const int gc = col0 + 4 * u;
        const float4 xz = *reinterpret_cast<const float4*>(&g_xz0[(size_t)bb * 6000 + gc]);
        const float4 b4v = *reinterpret_cast<const float4*>(&g_b0i[gc]);
        const float zi = xz.x + b4v.x, zj = xz.y + b4v.y;
        const float zo = xz.w + b4v.w;
        const float cn = sigmoidf_(zi) * tanhf(zj);
        const int ju = blockIdx.x * 12 + u;
        g_c0[bb * HID + ju] = cn;
        g_h0[0][bb * HROW + ju] = __float2bfloat16(tanhf(cn) * sigmoidf_(zo));
    }
    unsigned gen = 1;
    grid_barrier(gen);

#pragma unroll 1
    for (int t = 0; t < T; t++) {
        const int p = t & 1;
        const __nv_bfloat16* Ah0 = g_h0[p];        // h0(t)
        const __nv_bfloat16* Ah1 = g_h1[1 - p];    // h1(t-1)
        const __nv_bfloat16* W1a = g_W1i;
        const __nv_bfloat16* W1b = g_W1i + (size_t)1500 * 6000;

        auto issue = [&](int it) {
            const bool s1 = (it >= 24);
            const __nv_bfloat16* Ab = s1 ? Ah1 : Ah0;
            const __nv_bfloat16* Wb1 = s1 ? W1b : W1a;
            const int kk = (s1 ? (it - 24) : it) * 64;
            const int sb = it % RC_PIPE;
            // A tile: 64 rows x 64 K = 512 x 16B, 2 per thread
#pragma unroll
            for (int i = 0; i < 2; i++) {
                const int slot = tid + i * 256;
                const int row = slot >> 3, v = slot & 7;
                uint32_t da = (uint32_t)__cvta_generic_to_shared(&S->As[sb][row][v * 8]);
                const void* sa = Ab + (size_t)row * HROW + kk + v * 8;
                asm volatile("cp.async.cg.shared.global [%0], [%1], 16;" :: "r"(da), "l"(sa));
            }
            // B1 tile: 64 K x 48 cols = 384 x 16B; zero-fill K rows >= 1500
#pragma unroll
            for (int i = 0; i < 2; i++) {
                const int slot = tid + i * 256;
                if (slot < 384) {
                    const int row = slot / 6, v = slot % 6;
                    int krow = kk + row;
                    const int bytes = (krow < 1500) ? 16 : 0;
                    if (krow >= 1500) krow = 0;
                    uint32_t db1 = (uint32_t)__cvta_generic_to_shared(&S->Bs1[sb][row][v * 8]);
                    const void* sb1 = Wb1 + (size_t)krow * 6000 + col0 + v * 8;
                    asm volatile("cp.async.cg.shared.global [%0], [%1], 16, %2;"
                                 :: "r"(db1), "l"(sb1), "r"(bytes));
                }
            }
        };

        float accA[4][3][4], accB[4][3][4];
#pragma unroll
        for (int mt = 0; mt < 4; mt++)
#pragma unroll
            for (int nt = 0; nt < 3; nt++)
#pragma unroll
                for (int r = 0; r < 4; r++) { accA[mt][nt][r] = 0.0f; accB[mt][nt][r] = 0.0f; }

        issue(0);
        asm volatile("cp.async.commit_group;");
        issue(1);
        asm volatile("cp.async.commit_group;");

        const int ks = kg * 16;

#define MMA_(ACC, AT, R0, R1)                                                    \
    asm volatile("mma.sync.aligned.m16n8k16.row.col.f32.bf16.bf16.f32 "          \
                 "{%0,%1,%2,%3}, {%4,%5,%6,%7}, {%8,%9}, {%0,%1,%2,%3};"         \
                 : "+f"(ACC[0]), "+f"(ACC[1]), "+f"(ACC[2]), "+f"(ACC[3])        \
                 : "r"(AT[0]), "r"(AT[1]), "r"(AT[2]), "r"(AT[3]), "r"(R0), "r"(R1))

        // ---- segment 1: A=h0(t); accA from persistent Wp, accB from Bs1 ----
#pragma unroll 1
        for (int it = 0; it < 24; it++) {
            asm volatile("cp.async.wait_group 1;");
            __syncthreads();
            issue(it + 2);
            asm volatile("cp.async.commit_group;");

            const int b = it % RC_PIPE;
            const int kk = it * 64;
            uint32_t a4[4][4];
#pragma unroll
            for (int mt = 0; mt < 4; mt++) {
                uint32_t addr = (uint32_t)__cvta_generic_to_shared(
                    &S->As[b][mt * 16 + lrow][ks + lcol]);
                asm volatile("ldmatrix.sync.aligned.m8n8.x4.shared.b16 {%0,%1,%2,%3}, [%4];"
                    : "=r"(a4[mt][0]), "=r"(a4[mt][1]), "=r"(a4[mt][2]), "=r"(a4[mt][3])
                    : "r"(addr));
            }
            uint32_t b0q[4], b0d[2], b1q[4], b1d[2];
            {
                uint32_t addr = (uint32_t)__cvta_generic_to_shared(
                    &S->Wp[kk + ks + lrow][wn * 24 + lcol]);
                asm volatile("ldmatrix.sync.aligned.m8n8.x4.trans.shared.b16 {%0,%1,%2,%3}, [%4];"
                    : "=r"(b0q[0]), "=r"(b0q[1]), "=r"(b0q[2]), "=r"(b0q[3]) : "r"(addr));
                uint32_t addr2 = (uint32_t)__cvta_generic_to_shared(
                    &S->Wp[kk + ks + x2row][wn * 24 + 16]);
                asm volatile("ldmatrix.sync.aligned.m8n8.x2.trans.shared.b16 {%0,%1}, [%2];"
                    : "=r"(b0d[0]), "=r"(b0d[1]) : "r"(addr2));
            }
            {
                uint32_t addr = (uint32_t)__cvta_generic_to_shared(
                    &S->Bs1[b][ks + lrow][wn * 24 + lcol]);
                asm volatile("ldmatrix.sync.aligned.m8n8.x4.trans.shared.b16 {%0,%1,%2,%3}, [%4];"
                    : "=r"(b1q[0]), "=r"(b1q[1]), "=r"(b1q[2]), "=r"(b1q[3]) : "r"(addr));
                uint32_t addr2 = (uint32_t)__cvta_generic_to_shared(
                    &S->Bs1[b][ks + x2row][wn * 24 + 16]);
                asm volatile("ldmatrix.sync.aligned.m8n8.x2.trans.shared.b16 {%0,%1}, [%2];"
                    : "=r"(b1d[0]), "=r"(b1d[1]) : "r"(addr2));
            }
#pragma unroll
            for (int mt = 0; mt < 4; mt++) {
                MMA_(accA[mt][0], a4[mt], b0q[0], b0q[1]);
                MMA_(accA[mt][1], a4[mt], b0q[2], b0q[3]);
                MMA_(accA[mt][2], a4[mt], b0d[0], b0d[1]);
                MMA_(accB[mt][0], a4[mt], b1q[0], b1q[1]);
                MMA_(accB[mt][1], a4[mt], b1q[2], b1q[3]);
                MMA_(accB[mt][2], a4[mt], b1d[0], b1d[1]);
            }
        }

        // ---- segment 2: A=h1(t-1), Bs1->accB, 24 iters ----
#pragma unroll 1
        for (int it = 24; it < 48; it++) {
            asm volatile("cp.async.wait_group 1;");
            __syncthreads();
            if (it + 2 < 48) issue(it + 2);
            asm volatile("cp.async.commit_group;");

            const int b = it % RC_PIPE;
            uint32_t a4[4][4];
#pragma unroll
            for (int mt = 0; mt < 4; mt++) {
                uint32_t addr = (uint32_t)__cvta_generic_to_shared(
                    &S->As[b][mt * 16 + lrow][ks + lcol]);
                asm volatile("ldmatrix.sync.aligned.m8n8.x4.shared.b16 {%0,%1,%2,%3}, [%4];"
                    : "=r"(a4[mt][0]), "=r"(a4[mt][1]), "=r"(a4[mt][2]), "=r"(a4[mt][3])
                    : "r"(addr));
            }
            uint32_t b1q[4], b1d[2];
            {
                uint32_t addr = (uint32_t)__cvta_generic_to_shared(
                    &S->Bs1[b][ks + lrow][wn * 24 + lcol]);
                asm volatile("ldmatrix.sync.aligned.m8n8.x4.trans.shared.b16 {%0,%1,%2,%3}, [%4];"
                    : "=r"(b1q[0]), "=r"(b1q[1]), "=r"(b1q[2]), "=r"(b1q[3]) : "r"(addr));
                uint32_t addr2 = (uint32_t)__cvta_generic_to_shared(
                    &S->Bs1[b][ks + x2row][wn * 24 + 16]);
                asm volatile("ldmatrix.sync.aligned.m8n8.x2.trans.shared.b16 {%0,%1}, [%2];"
                    : "=r"(b1d[0]), "=r"(b1d[1]) : "r"(addr2));
            }
#pragma unroll
            for (int mt = 0; mt < 4; mt++) {
                MMA_(accB[mt][0], a4[mt], b1q[0], b1q[1]);
                MMA_(accB[mt][1], a4[mt], b1q[2], b1q[3]);
                MMA_(accB[mt][2], a4[mt], b1d[0], b1d[1]);
            }
        }
#undef MMA_

        const int r0m = lane >> 2;
        const int cbm = wn * 24 + (lane & 3) * 2;

        // ---- merge accB K-group partials into zs, then gates1(t) ----
        __syncthreads();
#pragma unroll 1
        for (int r = 0; r < 4; r++) {
            if (kg == r) {
#pragma unroll
                for (int mt = 0; mt < 4; mt++) {
                    const int rr = mt * 16 + r0m;
#pragma unroll
                    for (int nt = 0; nt < 3; nt++) {
                        const int cc = cbm + nt * 8;
                        if (r == 0) {
                            S->zs[rr][cc]     = accB[mt][nt][0];
                            S->zs[rr][cc + 1] = accB[mt][nt][1];
                            S->zs[rr + 8][cc]     = accB[mt][nt][2];
                            S->zs[rr + 8][cc + 1] = accB[mt][nt][3];
                        } else {
                            S->zs[rr][cc]     += accB[mt][nt][0];
                            S->zs[rr][cc + 1] += accB[mt][nt][1];
                            S->zs[rr + 8][cc]     += accB[mt][nt][2];
                            S->zs[rr + 8][cc + 1] += accB[mt][nt][3];
                        }
                    }
                }
            }
            __syncthreads();
        }
#pragma unroll
        for (int i = 0; i < 3; i++) {
            const int ul = i * 256 + tid;
            const int bb = ul / 12;
            const int u  = ul % 12;
            const float4 z4 = *reinterpret_cast<const float4*>(&S->zs[bb][4 * u]);
            const int gc = col0 + 4 * u;
            const float4 b4v = *reinterpret_cast<const float4*>(&g_b1i[gc]);
            const float zi = z4.x + b4v.x, zj = z4.y + b4v.y;
            const float zf = z4.z + b4v.z, zo = z4.w + b4v.w;
            const int ju = blockIdx.x * 12 + u;
            const float c = g_c1[bb * HID + ju];
            const float cn = c * sigmoidf_(zf + FORGET_BIAS) + sigmoidf_(zi) * tanhf(zj);
            g_c1[bb * HID + ju] = cn;
            const float h = tanhf(cn) * sigmoidf_(zo);
            const __nv_bfloat16 hb = __float2bfloat16(h);
            g_h1[p][bb * HROW + ju] = hb;
            g_out[(size_t)(t * B + bb) * KA + ju] = hb;
        }

        // ---- merge accA, then gates0(t+1) ----
        if (t < T - 1) {
            __syncthreads();
#pragma unroll 1
            for (int r = 0; r < 4; r++) {
                if (kg == r) {
#pragma unroll
                    for (int mt = 0; mt < 4; mt++) {
                        const int rr = mt * 16 + r0m;
#pragma unroll
                        for (int nt = 0; nt < 3; nt++) {
                            const int cc = cbm + nt * 8;
                            if (r == 0) {
                                S->zs[rr][cc]     = accA[mt][nt][0];
                                S->zs[rr][cc + 1] = accA[mt][nt][1];
                                S->zs[rr + 8][cc]     = accA[mt][nt][2];
                                S->zs[rr + 8][cc + 1] = accA[mt][nt][3];
                            } else {
                                S->zs[rr][cc]     += accA[mt][nt][0];
                                S->zs[rr][cc + 1] += accA[mt][nt][1];
                                S->zs[rr + 8][cc]     += accA[mt][nt][2];
                                S->zs[rr + 8][cc + 1] += accA[mt][nt][3];
                            }
                        }
                    }
                }
                __syncthreads();
            }
#pragma unroll
            for (int i = 0; i < 3; i++) {
                const int ul = i * 256 + tid;
                const int bb = ul / 12;
                const int u  = ul % 12;
                const float4 z4 = *reinterpret_cast<const float4*>(&S->zs[bb][4 * u]);
                const int gc = col0 + 4 * u;
                const float4 b4v = *reinterpret_cast<const float4*>(&g_b0i[gc]);
                const float4 xz = *reinterpret_cast<const float4*>(
                    &g_xz0[(size_t)((t + 1) * B + bb) * 6000 + gc]);
                const float zi = z4.x + b4v.x + xz.x, zj = z4.y + b4v.y + xz.y;
                const float zf = z4.z + b4v.z + xz.z, zo = z4.w + b4v.w + xz.w;
                const int ju = blockIdx.x * 12 + u;
                const float c = g_c0[bb * HID + ju];
                const float cn = c * sigmoidf_(zf + FORGET_BIAS) + sigmoidf_(zi) * tanhf(zj);
                g_c0[bb * HID + ju] = cn;
                const float h = tanhf(cn) * sigmoidf_(zo);
                g_h0[1 - p][bb * HROW + ju] = __float2bfloat16(h);
            }
        }

        gen++;
        grid_barrier(gen);
    }
}

// ---------------- log-softmax + NLL per row ----------------
__global__ void row_nll_kernel(const float* __restrict__ sb, const int* __restrict__ y) {
    __shared__ float red[256];
    const int row = blockIdx.x;
    const float* lr = g_logits + (size_t)row * VOCAB;
    float m = -1e30f;
    for (int v = threadIdx.x; v < VOCAB; v += 256) m = fmaxf(m, lr[v] + sb[v]);
    red[threadIdx.x] = m; __syncthreads();
    for (int s = 128; s > 0; s >>= 1) {
        if (threadIdx.x < s) red[threadIdx.x] = fmaxf(red[threadIdx.x], red[threadIdx.x + s]);
        __syncthreads();
    }
    m = red[0]; __syncthreads();
    float sum = 0.0f;
    for (int v = threadIdx.x; v < VOCAB; v += 256) sum += expf(lr[v] + sb[v] - m);
    red[threadIdx.x] = sum; __syncthreads();
    for (int s = 128; s > 0; s >>= 1) {
        if (threadIdx.x < s) red[threadIdx.x] += red[threadIdx.x + s];
        __syncthreads();
    }
    if (threadIdx.x == 0) {
        const int tgt = y[row];
        g_nll[row] = m + logf(red[0]) - (lr[tgt] + sb[tgt]);
    }
}

__global__ void final_loss_kernel(float* __restrict__ out) {
    __shared__ float red[256];
    float s = 0.0f;
    for (int i = threadIdx.x; i < T * B; i += 256) s += g_nll[i];
    red[threadIdx.x] = s; __syncthreads();
    for (int st = 128; st > 0; st >>= 1) {
        if (threadIdx.x < st) red[threadIdx.x] += red[threadIdx.x + st];
        __syncthreads();
    }
    if (threadIdx.x == 0) out[0] = red[0] / (float)B;
}

// ---------------- launch ----------------
extern "C" void kernel_launch(void* const* d_in, const int* in_sizes, int n_in,
                              void* d_out, int out_size) {
    const int*   x   = (const int*)d_in[0];
    const int*   y   = (const int*)d_in[1];
    const float* emb = (const float*)d_in[2];
    const float* W0  = (const float*)d_in[3];
    const float* b0  = (const float*)d_in[4];
    const float* W1  = (const float*)d_in[5];
    const float* b1  = (const float*)d_in[6];
    const float* sw  = (const float*)d_in[7];
    const float* sb  = (const float*)d_in[8];
    float* out = (float*)d_out;

    void *pW0i, *pSwb, *pInputs, *pOutB, *pXz0, *pLogits;
    cudaGetSymbolAddress(&pW0i, g_W0i);
    cudaGetSymbolAddress(&pSwb, g_swb);
    cudaGetSymbolAddress(&pInputs, g_inputs);
    cudaGetSymbolAddress(&pOutB, g_out);
    cudaGetSymbolAddress(&pXz0, g_xz0);
    cudaGetSymbolAddress(&pLogits, g_logits);

    static bool attrDone = false;
    if (!attrDone) {
        cudaFuncSetAttribute(gemm_pipe, cudaFuncAttributeMaxDynamicSharedMemorySize, GP_SMEM);
        cudaFuncSetAttribute(recurrence_kernel, cudaFuncAttributeMaxDynamicSharedMemorySize, RC_SMEM);
        attrDone = true;
    }

    // (1) fused prep (misc init + all weight conversions)  (2) embedding
    prep_all_kernel<<<2048, 256>>>(b0, b1, W0, W1, sw);
    embed_kernel<<<T * B, 128>>>(x, emb);

    // (3) prefix: xz0 = inputs @ W0i[0:EMB,:]  M=2240, N=6000, K=1500
    {
        dim3 grid((6000 + 127) / 128, (T * B + 127) / 128, 1);
        gemm_pipe<<<grid, 256, GP_SMEM>>>(
            (const __nv_bfloat16*)pInputs, (const __nv_bfloat16*)pW0i, (float*)pXz0,
            T * B, 6000, EMB, KA, 6000, 6000);
    }

    // (4) full recurrence (merged phases + persistent W0h in smem) — ncu slot 4
    recurrence_kernel<<<NBLK, 256, RC_SMEM>>>();

    // (5) logits = outputs @ softmax_w   M=2240, N=10000, K=1500
    {
        dim3 grid((VOCAB + 127) / 128, (T * B + 127) / 128, 1);
        gemm_pipe<<<grid, 256, GP_SMEM>>>(
            (const __nv_bfloat16*)pOutB, (const __nv_bfloat16*)pSwb, (float*)pLogits,
            T * B, VOCAB, HID, KA, VOCAB, VOCAB);
    }

    // (6,7) per-row log-softmax NLL + deterministic final reduction
    row_nll_kernel<<<T * B, 256>>>(sb, y);
    final_loss_kernel<<<1, 256>>>(out);
}

// round 15
// speedup vs baseline: 1.2695x; 1.2695x over previous
#include <cuda_runtime.h>
#include <cuda_bf16.h>
#include <math.h>
#include <stdint.h>

// Problem constants
constexpr int VOCAB = 10000;
constexpr int EMB   = 1500;
constexpr int HID   = 1500;
constexpr int T     = 35;
constexpr int B     = 64;
constexpr float FORGET_BIAS = 1.0f;

// Recurrence partitioning: 6000 gate cols = 125 blocks * 48 cols (12 hidden units * 4 gates)
constexpr int NBLK = 125;
constexpr int CPB  = 48;   // cols per block
constexpr int HROW = 1536; // padded row stride for h buffers (multiple of 64)
constexpr int KA   = 1504; // padded activation row stride

// ---------------- static device scratch ----------------
__device__ __align__(128) float g_xz0[(size_t)T * B * 6000];       // interleaved cols
__device__ __align__(128) float g_logits[(size_t)T * B * VOCAB];
__device__ __align__(128) float g_c0[B * HID];
__device__ __align__(128) float g_c1[B * HID];
__device__ __align__(128) float g_nll[T * B];
__device__ __align__(128) float g_b0i[6000];
__device__ __align__(128) float g_b1i[6000];
__device__ __align__(128) __nv_bfloat16 g_inputs[(size_t)T * B * KA];      // padded rows
__device__ __align__(128) __nv_bfloat16 g_W0i[(size_t)(EMB + HID) * 6000]; // gate-interleaved
__device__ __align__(128) __nv_bfloat16 g_W1i[(size_t)2 * HID * 6000];     // gate-interleaved
__device__ __align__(128) __nv_bfloat16 g_swb[(size_t)HID * VOCAB];
__device__ __align__(128) __nv_bfloat16 g_h0[2][B * HROW];  // ping-pong h0
__device__ __align__(128) __nv_bfloat16 g_h1[2][B * HROW];  // ping-pong h1
__device__ __align__(128) __nv_bfloat16 g_out[(size_t)T * B * KA];         // padded rows
__device__ unsigned g_barCount;
__device__ unsigned g_barGen;

__device__ __forceinline__ float sigmoidf_(float x) {
    return 1.0f / (1.0f + expf(-x));
}

// ---------------- fused prep: misc init + ALL weight conversions ----------------
__global__ void prep_all_kernel(const float* __restrict__ b0, const float* __restrict__ b1,
                                const float* __restrict__ W0, const float* __restrict__ W1,
                                const float* __restrict__ sw) {
    constexpr int N0 = (EMB + HID) * 1500;   // W0 (row, unit) pairs
    constexpr int N1 = 2 * HID * 1500;       // W1
    constexpr int N2 = HID * VOCAB / 2;      // sw float2 pairs
    const int i0 = blockIdx.x * blockDim.x + threadIdx.x;

    if (i0 == 0) { g_barCount = 0u; g_barGen = 0u; }
    const __nv_bfloat16 z = __float2bfloat16(0.0f);
    if (i0 < B * HROW) {
        g_h0[0][i0] = z; g_h0[1][i0] = z;
        g_h1[0][i0] = z; g_h1[1][i0] = z;
    }
    if (i0 < B * HID) { g_c0[i0] = 0.0f; g_c1[i0] = 0.0f; }
    if (i0 < T * B * 4) {
        const int r = i0 >> 2, c = i0 & 3;
        g_out[(size_t)r * KA + 1500 + c] = z;
    }
    if (i0 < 6000) {
        const int g = i0 / 1500, j = i0 % 1500;
        g_b0i[4 * j + g] = b0[i0];
        g_b1i[4 * j + g] = b1[i0];
    }

    long long i = i0;
    const long long stride = gridDim.x * (long long)blockDim.x;
    for (; i < (long long)N0 + N1 + N2; i += stride) {
        if (i < N0) {
            const int r = (int)(i / 1500), j = (int)(i % 1500);
            const float* s = W0 + (size_t)r * 6000;
            const __nv_bfloat162 p0 = __floats2bfloat162_rn(s[j], s[1500 + j]);
            const __nv_bfloat162 p1 = __floats2bfloat162_rn(s[3000 + j], s[4500 + j]);
            uint2 pk;
            pk.x = *reinterpret_cast<const uint32_t*>(&p0);
            pk.y = *reinterpret_cast<const uint32_t*>(&p1);
            *reinterpret_cast<uint2*>(g_W0i + (size_t)r * 6000 + 4 * j) = pk;
        } else if (i < (long long)N0 + N1) {
            const int ii = (int)(i - N0);
            const int r = ii / 1500, j = ii % 1500;
            const float* s = W1 + (size_t)r * 6000;
            const __nv_bfloat162 p0 = __floats2bfloat162_rn(s[j], s[1500 + j]);
            const __nv_bfloat162 p1 = __floats2bfloat162_rn(s[3000 + j], s[4500 + j]);
            uint2 pk;
            pk.x = *reinterpret_cast<const uint32_t*>(&p0);
            pk.y = *reinterpret_cast<const uint32_t*>(&p1);
            *reinterpret_cast<uint2*>(g_W1i + (size_t)r * 6000 + 4 * j) = pk;
        } else {
            const int ii = (int)(i - N0 - N1);
            const float2 v = reinterpret_cast<const float2*>(sw)[ii];
            reinterpret_cast<__nv_bfloat162*>(g_swb)[ii] = __floats2bfloat162_rn(v.x, v.y);
        }
    }
}

// embedding gather into padded rows (pad cols zeroed)
__global__ void embed_kernel(const int* __restrict__ x, const float* __restrict__ emb) {
    const int row = blockIdx.x;
    const int tok = x[row];
    const float2* src = reinterpret_cast<const float2*>(emb + (size_t)tok * EMB);
    __nv_bfloat162* dst = reinterpret_cast<__nv_bfloat162*>(g_inputs + (size_t)row * KA);
    for (int i = threadIdx.x; i < KA / 2; i += blockDim.x) {
        if (i < EMB / 2) {
            float2 v = src[i];
            dst[i] = __floats2bfloat162_rn(v.x, v.y);
        } else {
            dst[i] = __floats2bfloat162_rn(0.0f, 0.0f);
        }
    }
}

// ---------------- pipelined bf16 tensor-core GEMM (big batched GEMMs) ----------------
constexpr int GP_PIPE = 3;
constexpr int GP_SMEM = GP_PIPE * (128 * 40 + 32 * 136) * 2;  // 56832 bytes

__global__ void __launch_bounds__(256, 2)
gemm_pipe(const __nv_bfloat16* __restrict__ A, const __nv_bfloat16* __restrict__ Bm,
          float* __restrict__ C, int M, int N, int K,
          int lda, int ldb, int ldc)
{
    extern __shared__ char dynsmem[];
    typedef __nv_bfloat16 (*AsT)[128][40];
    typedef __nv_bfloat16 (*BsT)[32][136];
    AsT As = reinterpret_cast<AsT>(dynsmem);
    BsT Bs = reinterpret_cast<BsT>(dynsmem + GP_PIPE * 128 * 40 * 2);

    const int tid = threadIdx.x;
    const int lane = tid & 31;
    const int warp = tid >> 5;
    const int wm = warp >> 2;
    const int wn = warp & 3;
    const int row0 = blockIdx.y * 128;
    const int col0 = blockIdx.x * 128;
    const int KITER = (K + 31) / 32;

    const int arow = tid >> 2;
    const int acol = (tid & 3) * 8;
    const int brow = tid >> 4;
    const int bcol = (tid & 15) * 8;

    const int lrow = ((lane >> 3) & 1) * 8 + (lane & 7);
    const int lcol = (lane >> 4) * 8;

    float acc[4][4][4];
#pragma unroll
    for (int mt = 0; mt < 4; mt++)
#pragma unroll
        for (int nt = 0; nt < 4; nt++)
#pragma unroll
            for (int r = 0; r < 4; r++) acc[mt][nt][r] = 0.0f;

    auto issue = [&](int it) {
        const int k0 = it * 32;
        const int sb = it % GP_PIPE;
#pragma unroll
        for (int h = 0; h < 2; h++) {
            const int r = arow + h * 64;
            const int gr = row0 + r;
            const int grc = min(gr, M - 1);
            const int bytes = (gr < M) ? 16 : 0;
            uint32_t da = (uint32_t)__cvta_generic_to_shared(&As[sb][r][acol]);
            const void* sa = A + (size_t)grc * lda + k0 + acol;
            asm volatile("cp.async.cg.shared.global [%0], [%1], 16, %2;"
                         :: "r"(da), "l"(sa), "r"(bytes));
        }
#pragma unroll
        for (int h = 0; h < 2; h++) {
            const int r = brow + h * 16;
            const int gk = k0 + r;
            const int gc = col0 + bcol;
            const int bytes = (gk < K && gc < N) ? 16 : 0;
            const int gkc = min(gk, K - 1);
            const int gcc = min(gc, N - 8);
            uint32_t db = (uint32_t)__cvta_generic_to_shared(&Bs[sb][r][bcol]);
            const void* sbp = Bm + (size_t)gkc * ldb + gcc;
            asm volatile("cp.async.cg.shared.global [%0], [%1], 16, %2;"
                         :: "r"(db), "l"(sbp), "r"(bytes));
        }
    };

    issue(0);
    asm volatile("cp.async.commit_group;");
    issue(1);
    asm volatile("cp.async.commit_group;");

#pragma unroll 1
    for (int it = 0; it < KITER; it++) {
        asm volatile("cp.async.wait_group 1;");
        __syncthreads();
        if (it + 2 < KITER) issue(it + 2);
        asm volatile("cp.async.commit_group;");

        const int b = it % GP_PIPE;
#pragma unroll
        for (int ks = 0; ks < 32; ks += 16) {
            uint32_t ar[4][4];
            uint32_t br[2][4];
#pragma unroll
            for (int mt = 0; mt < 4; mt++) {
                uint32_t addr = (uint32_t)__cvta_generic_to_shared(
                    &As[b][wm * 64 + mt * 16 + lrow][ks + lcol]);
                asm volatile("ldmatrix.sync.aligned.m8n8.x4.shared.b16 {%0,%1,%2,%3}, [%4];"
                    : "=r"(ar[mt][0]), "=r"(ar[mt][1]), "=r"(ar[mt][2]), "=r"(ar[mt][3])
                    : "r"(addr));
            }
#pragma unroll
            for (int q = 0; q < 2; q++) {
                uint32_t addr = (uint32_t)__cvta_generic_to_shared(
                    &Bs[b][ks + lrow][wn * 32 + q * 16 + lcol]);
                asm volatile("ldmatrix.sync.aligned.m8n8.x4.trans.shared.b16 {%0,%1,%2,%3}, [%4];"
                    : "=r"(br[q][0]), "=r"(br[q][1]), "=r"(br[q][2]), "=r"(br[q][3])
                    : "r"(addr));
            }
#pragma unroll
            for (int mt = 0; mt < 4; mt++)
#pragma unroll
                for (int nt = 0; nt < 4; nt++) {
                    const int q = nt >> 1;
                    const int p = (nt & 1) * 2;
                    asm volatile(
                        "mma.sync.aligned.m16n8k16.row.col.f32.bf16.bf16.f32 "
                        "{%0,%1,%2,%3}, {%4,%5,%6,%7}, {%8,%9}, {%0,%1,%2,%3};"
                        : "+f"(acc[mt][nt][0]), "+f"(acc[mt][nt][1]),
                          "+f"(acc[mt][nt][2]), "+f"(acc[mt][nt][3])
                        : "r"(ar[mt][0]), "r"(ar[mt][1]), "r"(ar[mt][2]), "r"(ar[mt][3]),
                          "r"(br[q][p]), "r"(br[q][p + 1]));
                }
        }
    }

#pragma unroll
    for (int mt = 0; mt < 4; mt++) {
        const int r0 = row0 + wm * 64 + mt * 16 + (lane >> 2);
#pragma unroll
        for (int nt = 0; nt < 4; nt++) {
            const int c = col0 + wn * 32 + nt * 8 + (lane & 3) * 2;
            if (c < N) {
                if (r0 < M) {
                    C[(long long)r0 * ldc + c]     = acc[mt][nt][0];
                    C[(long long)r0 * ldc + c + 1] = acc[mt][nt][1];
                }
                if (r0 + 8 < M) {
                    C[(long long)(r0 + 8) * ldc + c]     = acc[mt][nt][2];
                    C[(long long)(r0 + 8) * ldc + c + 1] = acc[mt][nt][3];
                }
            }
        }
    }
}

// ---------------- lightweight grid barrier ----------------
__device__ __forceinline__ void grid_barrier(unsigned target) {
    __syncthreads();
    if (threadIdx.x == 0) {
        unsigned a;
        asm volatile("atom.add.release.gpu.u32 %0, [%1], %2;"
                     : "=r"(a) : "l"(&g_barCount), "r"(1u) : "memory");
        if (a == (unsigned)(NBLK - 1)) {
            g_barCount = 0u;
            asm volatile("st.release.gpu.u32 [%0], %1;" :: "l"(&g_barGen), "r"(target) : "memory");
        } else {
            unsigned g;
            do {
                asm volatile("ld.acquire.gpu.u32 %0, [%1];" : "=r"(g) : "l"(&g_barGen) : "memory");
            } while ((int)(g - target) < 0);
        }
    }
    __syncthreads();
}

// ---------------- persistent recurrence: merged phases + W0h persisted in smem ----------------
// W0h persisted at stride 56 elems (112 B): 16B-aligned (fixes R14's fault),
// degree-2 ldsm conflicts — identical to the proven Bs1 layout. Smem budget met
// by aliasing zs onto the As stage buffers (zs only live in the epilogue, after
// all As reads and after cp.async groups drain).
constexpr int RC_PIPE = 3;
constexpr int WPS = 56;   // Wp row stride (elems): 112 B, 16B-aligned, degree-2
struct RcSmem {
    __nv_bfloat16 Wp[1536][WPS];          // 172032 B persistent W0h cols
    __nv_bfloat16 As[RC_PIPE][64][72];    // 27648 B (zs aliases this region)
    __nv_bfloat16 Bs1[RC_PIPE][64][56];   // 21504 B
};
constexpr int RC_SMEM = sizeof(RcSmem);   // 221184 bytes

__global__ void __launch_bounds__(256, 1) recurrence_kernel() {
    extern __shared__ char dynsmem[];
    RcSmem* S = reinterpret_cast<RcSmem*>(dynsmem);
    // zs aliases the As stage buffers (13312 B <= 27648 B); only live in epilogue.
    typedef float (*ZsT)[52];
    ZsT zs = reinterpret_cast<ZsT>(&S->As[0][0][0]);

    const int tid = threadIdx.x;
    const int lane = tid & 31;
    const int warp = tid >> 5;
    const int kg = warp >> 1;        // 0..3  K-group
    const int wn = warp & 1;         // 0..1  N-half
    const int col0 = blockIdx.x * CPB;
    const int lrow = ((lane >> 3) & 1) * 8 + (lane & 7);
    const int lcol = (lane >> 4) * 8;
    const int x2row = lane & 15;

    const __nv_bfloat16* W0h = g_W0i + (size_t)EMB * 6000;

    // -------- load persistent W0h block columns into smem (stride WPS) --------
    {
        for (int slot = tid; slot < 36 * 6; slot += 256) {
            const int row = 1500 + slot / 6, v = slot % 6;
            *reinterpret_cast<uint4*>(&S->Wp[row][v * 8]) = make_uint4(0u, 0u, 0u, 0u);
        }
        for (int idx = tid; idx < 1500 * 6; idx += 256) {
            const int row = idx / 6, v = idx % 6;
            uint32_t d = (uint32_t)__cvta_generic_to_shared(&S->Wp[row][v * 8]);
            const void* s = W0h + (size_t)row * 6000 + col0 + v * 8;
            asm volatile("cp.async.cg.shared.global [%0], [%1], 16;" :: "r"(d), "l"(s));
        }
        asm volatile("cp.async.commit_group;");
        asm volatile("cp.async.wait_group 0;");
    }

    // -------- bootstrap: gates0(0) from xz0(0)+b0 (h(-1)=0, c=0) --------
#pragma unroll
    for (int i = 0; i < 3; i++) {
        const int ul = i * 256 + tid;
        const int bb = ul / 12;
        const int u  = ul % 12;
        const int gc = col0 + 4 * u;
        const float4 xz = *reinterpret_cast<const float4*>(&g_xz0[(size_t)bb * 6000 + gc]);
        const float4 b4v = *reinterpret_cast<const float4*>(&g_b0i[gc]);
        const float zi = xz.x + b4v.x, zj = xz.y + b4v.y;
        const float zo = xz.w + b4v.w;
        const float cn = sigmoidf_(zi) * tanhf(zj);
        const int ju = blockIdx.x * 12 + u;
        g_c0[bb * HID + ju] = cn;
        g_h0[0][bb * HROW + ju] = __float2bfloat16(tanhf(cn) * sigmoidf_(zo));
    }
    unsigned gen = 1;
    grid_barrier(gen);

#pragma unroll 1
    for (int t = 0; t < T; t++) {
        const int p = t & 1;
        const __nv_bfloat16* Ah0 = g_h0[p];        // h0(t)
        const __nv_bfloat16* Ah1 = g_h1[1 - p];    // h1(t-1)
        const __nv_bfloat16* W1a = g_W1i;
        const __nv_bfloat16* W1b = g_W1i + (size_t)1500 * 6000;

        auto issue = [&](int it) {
            const bool s1 = (it >= 24);
            const __nv_bfloat16* Ab = s1 ? Ah1 : Ah0;
            const __nv_bfloat16* Wb1 = s1 ? W1b : W1a;
            const int kk = (s1 ? (it - 24) : it) * 64;
            const int sb = it % RC_PIPE;
            // A tile: 64 rows x 64 K = 512 x 16B, 2 per thread
#pragma unroll
            for (int i = 0; i < 2; i++) {
                const int slot = tid + i * 256;
                const int row = slot >> 3, v = slot & 7;
                uint32_t da = (uint32_t)__cvta_generic_to_shared(&S->As[sb][row][v * 8]);
                const void* sa = Ab + (size_t)row * HROW + kk + v * 8;
                asm volatile("cp.async.cg.shared.global [%0], [%1], 16;" :: "r"(da), "l"(sa));
            }
            // B1 tile: 64 K x 48 cols = 384 x 16B; zero-fill K rows >= 1500
#pragma unroll
            for (int i = 0; i < 2; i++) {
                const int slot = tid + i * 256;
                if (slot < 384) {
                    const int row = slot / 6, v = slot % 6;
                    int krow = kk + row;
                    const int bytes = (krow < 1500) ? 16 : 0;
                    if (krow >= 1500) krow = 0;
                    uint32_t db1 = (uint32_t)__cvta_generic_to_shared(&S->Bs1[sb][row][v * 8]);
                    const void* sb1 = Wb1 + (size_t)krow * 6000 + col0 + v * 8;
                    asm volatile("cp.async.cg.shared.global [%0], [%1], 16, %2;"
                                 :: "r"(db1), "l"(sb1), "r"(bytes));
                }
            }
        };

        float accA[4][3][4], accB[4][3][4];
#pragma unroll
        for (int mt = 0; mt < 4; mt++)
#pragma unroll
            for (int nt = 0; nt < 3; nt++)
#pragma unroll
                for (int r = 0; r < 4; r++) { accA[mt][nt][r] = 0.0f; accB[mt][nt][r] = 0.0f; }

        issue(0);
        asm volatile("cp.async.commit_group;");
        issue(1);
        asm volatile("cp.async.commit_group;");

        const int ks = kg * 16;

#define MMA_(ACC, AT, R0, R1)                                                    \
    asm volatile("mma.sync.aligned.m16n8k16.row.col.f32.bf16.bf16.f32 "          \
                 "{%0,%1,%2,%3}, {%4,%5,%6,%7}, {%8,%9}, {%0,%1,%2,%3};"         \
                 : "+f"(ACC[0]), "+f"(ACC[1]), "+f"(ACC[2]), "+f"(ACC[3])        \
                 : "r"(AT[0]), "r"(AT[1]), "r"(AT[2]), "r"(AT[3]), "r"(R0), "r"(R1))

        // ---- segment 1: A=h0(t); accA from persistent Wp, accB from Bs1 ----
#pragma unroll 1
        for (int it = 0; it < 24; it++) {
            asm volatile("cp.async.wait_group 1;");
            __syncthreads();
            issue(it + 2);
            asm volatile("cp.async.commit_group;");

            const int b = it % RC_PIPE;
            const int kk = it * 64;
            uint32_t a4[4][4];
#pragma unroll
            for (int mt = 0; mt < 4; mt++) {
                uint32_t addr = (uint32_t)__cvta_generic_to_shared(
                    &S->As[b][mt * 16 + lrow][ks + lcol]);
                asm volatile("ldmatrix.sync.aligned.m8n8.x4.shared.b16 {%0,%1,%2,%3}, [%4];"
                    : "=r"(a4[mt][0]), "=r"(a4[mt][1]), "=r"(a4[mt][2]), "=r"(a4[mt][3])
                    : "r"(addr));
            }
            uint32_t b0q[4], b0d[2], b1q[4], b1d[2];
            {
                uint32_t addr = (uint32_t)__cvta_generic_to_shared(
                    &S->Wp[kk + ks + lrow][wn * 24 + lcol]);
                asm volatile("ldmatrix.sync.aligned.m8n8.x4.trans.shared.b16 {%0,%1,%2,%3}, [%4];"
                    : "=r"(b0q[0]), "=r"(b0q[1]), "=r"(b0q[2]), "=r"(b0q[3]) : "r"(addr));
                uint32_t addr2 = (uint32_t)__cvta_generic_to_shared(
                    &S->Wp[kk + ks + x2row][wn * 24 + 16]);
                asm volatile("ldmatrix.sync.aligned.m8n8.x2.trans.shared.b16 {%0,%1}, [%2];"
                    : "=r"(b0d[0]), "=r"(b0d[1]) : "r"(addr2));
            }
            {
                uint32_t addr = (uint32_t)__cvta_generic_to_shared(
                    &S->Bs1[b][ks + lrow][wn * 24 + lcol]);
                asm volatile("ldmatrix.sync.aligned.m8n8.x4.trans.shared.b16 {%0,%1,%2,%3}, [%4];"
                    : "=r"(b1q[0]), "=r"(b1q[1]), "=r"(b1q[2]), "=r"(b1q[3]) : "r"(addr));
                uint32_t addr2 = (uint32_t)__cvta_generic_to_shared(
                    &S->Bs1[b][ks + x2row][wn * 24 + 16]);
                asm volatile("ldmatrix.sync.aligned.m8n8.x2.trans.shared.b16 {%0,%1}, [%2];"
                    : "=r"(b1d[0]), "=r"(b1d[1]) : "r"(addr2));
            }
#pragma unroll
            for (int mt = 0; mt < 4; mt++) {
                MMA_(accA[mt][0], a4[mt], b0q[0], b0q[1]);
                MMA_(accA[mt][1], a4[mt], b0q[2], b0q[3]);
                MMA_(accA[mt][2], a4[mt], b0d[0], b0d[1]);
                MMA_(accB[mt][0], a4[mt], b1q[0], b1q[1]);
                MMA_(accB[mt][1], a4[mt], b1q[2], b1q[3]);
                MMA_(accB[mt][2], a4[mt], b1d[0], b1d[1]);
            }
        }

        // ---- segment 2: A=h1(t-1), Bs1->accB, 24 iters ----
#pragma unroll 1
        for (int it = 24; it < 48; it++) {
            asm volatile("cp.async.wait_group 1;");
            __syncthreads();
            if (it + 2 < 48) issue(it + 2);
            asm volatile("cp.async.commit_group;");

            const int b = it % RC_PIPE;
            uint32_t a4[4][4];
#pragma unroll
            for (int mt = 0; mt < 4; mt++) {
                uint32_t addr = (uint32_t)__cvta_generic_to_shared(
                    &S->As[b][mt * 16 + lrow][ks + lcol]);
                asm volatile("ldmatrix.sync.aligned.m8n8.x4.shared.b16 {%0,%1,%2,%3}, [%4];"
                    : "=r"(a4[mt][0]), "=r"(a4[mt][1]), "=r"(a4[mt][2]), "=r"(a4[mt][3])
                    : "r"(addr));
            }
            uint32_t b1q[4], b1d[2];
            {
                uint32_t addr = (uint32_t)__cvta_generic_to_shared(
                    &S->Bs1[b][ks + lrow][wn * 24 + lcol]);
                asm volatile("ldmatrix.sync.aligned.m8n8.x4.trans.shared.b16 {%0,%1,%2,%3}, [%4];"
                    : "=r"(b1q[0]), "=r"(b1q[1]), "=r"(b1q[2]), "=r"(b1q[3]) : "r"(addr));
                uint32_t addr2 = (uint32_t)__cvta_generic_to_shared(
                    &S->Bs1[b][ks + x2row][wn * 24 + 16]);
                asm volatile("ldmatrix.sync.aligned.m8n8.x2.trans.shared.b16 {%0,%1}, [%2];"
                    : "=r"(b1d[0]), "=r"(b1d[1]) : "r"(addr2));
            }
#pragma unroll
            for (int mt = 0; mt < 4; mt++) {
                MMA_(accB[mt][0], a4[mt], b1q[0], b1q[1]);
                MMA_(accB[mt][1], a4[mt], b1q[2], b1q[3]);
                MMA_(accB[mt][2], a4[mt], b1d[0], b1d[1]);
            }
        }
#undef MMA_

        // drain any remaining (empty) cp.async groups before zs aliases As
        asm volatile("cp.async.wait_group 0;");

        const int r0m = lane >> 2;
        const int cbm = wn * 24 + (lane & 3) * 2;

        // ---- merge accB K-group partials into zs, then gates1(t) ----
        __syncthreads();
#pragma unroll 1
        for (int r = 0; r < 4; r++) {
            if (kg == r) {
#pragma unroll
                for (int mt = 0; mt < 4; mt++) {
                    const int rr = mt * 16 + r0m;
#pragma unroll
                    for (int nt = 0; nt < 3; nt++) {
                        const int cc = cbm + nt * 8;
                        if (r == 0) {
                            zs[rr][cc]     = accB[mt][nt][0];
                            zs[rr][cc + 1] = accB[mt][nt][1];
                            zs[rr + 8][cc]     = accB[mt][nt][2];
                            zs[rr + 8][cc + 1] = accB[mt][nt][3];
                        } else {
                            zs[rr][cc]     += accB[mt][nt][0];
                            zs[rr][cc + 1] += accB[mt][nt][1];
                            zs[rr + 8][cc]     += accB[mt][nt][2];
                            zs[rr + 8][cc + 1] += accB[mt][nt][3];
                        }
                    }
                }
            }
            __syncthreads();
        }
#pragma unroll
        for (int i = 0; i < 3; i++) {
            const int ul = i * 256 + tid;
            const int bb = ul / 12;
            const int u  = ul % 12;
            const float4 z4 = *reinterpret_cast<const float4*>(&zs[bb][4 * u]);
            const int gc = col0 + 4 * u;
            const float4 b4v = *reinterpret_cast<const float4*>(&g_b1i[gc]);
            const float zi = z4.x + b4v.x, zj = z4.y + b4v.y;
            const float zf = z4.z + b4v.z, zo = z4.w + b4v.w;
            const int ju = blockIdx.x * 12 + u;
            const float c = g_c1[bb * HID + ju];
            const float cn = c * sigmoidf_(zf + FORGET_BIAS) + sigmoidf_(zi) * tanhf(zj);
            g_c1[bb * HID + ju] = cn;
            const float h = tanhf(cn) * sigmoidf_(zo);
            const __nv_bfloat16 hb = __float2bfloat16(h);
            g_h1[p][bb * HROW + ju] = hb;
            g_out[(size_t)(t * B + bb) * KA + ju] = hb;
        }

        // ---- merge accA, then gates0(t+1) ----
        if (t < T - 1) {
            __syncthreads();
#pragma unroll 1
            for (int r = 0; r < 4; r++) {
                if (kg == r) {
#pragma unroll
                    for (int mt = 0; mt < 4; mt++) {
                        const int rr = mt * 16 + r0m;
#pragma unroll
                        for (int nt = 0; nt < 3; nt++) {
                            const int cc = cbm + nt * 8;
                            if (r == 0) {
                                zs[rr][cc]     = accA[mt][nt][0];
                                zs[rr][cc + 1] = accA[mt][nt][1];
                                zs[rr + 8][cc]     = accA[mt][nt][2];
                                zs[rr + 8][cc + 1] = accA[mt][nt][3];
                            } else {
                                zs[rr][cc]     += accA[mt][nt][0];
                                zs[rr][cc + 1] += accA[mt][nt][1];
                                zs[rr + 8][cc]     += accA[mt][nt][2];
                                zs[rr + 8][cc + 1] += accA[mt][nt][3];
                            }
                        }
                    }
                }
                __syncthreads();
            }
#pragma unroll
            for (int i = 0; i < 3; i++) {
                const int ul = i * 256 + tid;
                const int bb = ul / 12;
                const int u  = ul % 12;
                const float4 z4 = *reinterpret_cast<const float4*>(&zs[bb][4 * u]);
                const int gc = col0 + 4 * u;
                const float4 b4v = *reinterpret_cast<const float4*>(&g_b0i[gc]);
                const float4 xz = *reinterpret_cast<const float4*>(
                    &g_xz0[(size_t)((t + 1) * B + bb) * 6000 + gc]);
                const float zi = z4.x + b4v.x + xz.x, zj = z4.y + b4v.y + xz.y;
                const float zf = z4.z + b4v.z + xz.z, zo = z4.w + b4v.w + xz.w;
                const int ju = blockIdx.x * 12 + u;
                const float c = g_c0[bb * HID + ju];
                const float cn = c * sigmoidf_(zf + FORGET_BIAS) + sigmoidf_(zi) * tanhf(zj);
                g_c0[bb * HID + ju] = cn;
                const float h = tanhf(cn) * sigmoidf_(zo);
                g_h0[1 - p][bb * HROW + ju] = __float2bfloat16(h);
            }
        }

        gen++;
        grid_barrier(gen);
    }
}

// ---------------- log-softmax + NLL per row ----------------
__global__ void row_nll_kernel(const float* __restrict__ sb, const int* __restrict__ y) {
    __shared__ float red[256];
    const int row = blockIdx.x;
    const float* lr = g_logits + (size_t)row * VOCAB;
    float m = -1e30f;
    for (int v = threadIdx.x; v < VOCAB; v += 256) m = fmaxf(m, lr[v] + sb[v]);
    red[threadIdx.x] = m; __syncthreads();
    for (int s = 128; s > 0; s >>= 1) {
        if (threadIdx.x < s) red[threadIdx.x] = fmaxf(red[threadIdx.x], red[threadIdx.x + s]);
        __syncthreads();
    }
    m = red[0]; __syncthreads();
    float sum = 0.0f;
    for (int v = threadIdx.x; v < VOCAB; v += 256) sum += expf(lr[v] + sb[v] - m);
    red[threadIdx.x] = sum; __syncthreads();
    for (int s = 128; s > 0; s >>= 1) {
        if (threadIdx.x < s) red[threadIdx.x] += red[threadIdx.x + s];
        __syncthreads();
    }
    if (threadIdx.x == 0) {
        const int tgt = y[row];
        g_nll[row] = m + logf(red[0]) - (lr[tgt] + sb[tgt]);
    }
}

__global__ void final_loss_kernel(float* __restrict__ out) {
    __shared__ float red[256];
    float s = 0.0f;
    for (int i = threadIdx.x; i < T * B; i += 256) s += g_nll[i];
    red[threadIdx.x] = s; __syncthreads();
    for (int st = 128; st > 0; st >>= 1) {
        if (threadIdx.x < st) red[threadIdx.x] += red[threadIdx.x + st];
        __syncthreads();
    }
    if (threadIdx.x == 0) out[0] = red[0] / (float)B;
}

// ---------------- launch ----------------
extern "C" void kernel_launch(void* const* d_in, const int* in_sizes, int n_in,
                              void* d_out, int out_size) {
    const int*   x   = (const int*)d_in[0];
    const int*   y   = (const int*)d_in[1];
    const float* emb = (const float*)d_in[2];
    const float* W0  = (const float*)d_in[3];
    const float* b0  = (const float*)d_in[4];
    const float* W1  = (const float*)d_in[5];
    const float* b1  = (const float*)d_in[6];
    const float* sw  = (const float*)d_in[7];
    const float* sb  = (const float*)d_in[8];
    float* out = (float*)d_out;

    void *pW0i, *pSwb, *pInputs, *pOutB, *pXz0, *pLogits;
    cudaGetSymbolAddress(&pW0i, g_W0i);
    cudaGetSymbolAddress(&pSwb, g_swb);
    cudaGetSymbolAddress(&pInputs, g_inputs);
    cudaGetSymbolAddress(&pOutB, g_out);
    cudaGetSymbolAddress(&pXz0, g_xz0);
    cudaGetSymbolAddress(&pLogits, g_logits);

    static bool attrDone = false;
    if (!attrDone) {
        cudaFuncSetAttribute(gemm_pipe, cudaFuncAttributeMaxDynamicSharedMemorySize, GP_SMEM);
        cudaFuncSetAttribute(recurrence_kernel, cudaFuncAttributeMaxDynamicSharedMemorySize, RC_SMEM);
        attrDone = true;
    }

    // (1) fused prep (misc init + all weight conversions)  (2) embedding
    prep_all_kernel<<<2048, 256>>>(b0, b1, W0, W1, sw);
    embed_kernel<<<T * B, 128>>>(x, emb);

    // (3) prefix: xz0 = inputs @ W0i[0:EMB,:]  M=2240, N=6000, K=1500
    {
        dim3 grid((6000 + 127) / 128, (T * B + 127) / 128, 1);
        gemm_pipe<<<grid, 256, GP_SMEM>>>(
            (const __nv_bfloat16*)pInputs, (const __nv_bfloat16*)pW0i, (float*)pXz0,
            T * B, 6000, EMB, KA, 6000, 6000);
    }

    // (4) full recurrence (merged phases + aligned persistent W0h, zs aliased)
    recurrence_kernel<<<NBLK, 256, RC_SMEM>>>();

    // (5) logits = outputs @ softmax_w   M=2240, N=10000, K=1500
    {
        dim3 grid((VOCAB + 127) / 128, (T * B + 127) / 128, 1);
        gemm_pipe<<<grid, 256, GP_SMEM>>>(
            (const __nv_bfloat16*)pOutB, (const __nv_bfloat16*)pSwb, (float*)pLogits,
            T * B, VOCAB, HID, KA, VOCAB, VOCAB);
    }

    // (6,7) per-row log-softmax NLL + deterministic final reduction
    row_nll_kernel<<<T * B, 256>>>(sb, y);
    final_loss_kernel<<<1, 256>>>(out);
}

// round 16
// speedup vs baseline: 1.2718x; 1.0018x over previous
#include <cuda_runtime.h>
#include <cuda_bf16.h>
#include <math.h>
#include <stdint.h>

// Problem constants
constexpr int VOCAB = 10000;
constexpr int EMB   = 1500;
constexpr int HID   = 1500;
constexpr int T     = 35;
constexpr int B     = 64;
constexpr float FORGET_BIAS = 1.0f;

// Recurrence partitioning: 6000 gate cols = 125 blocks * 48 cols (12 hidden units * 4 gates)
constexpr int NBLK = 125;
constexpr int CPB  = 48;   // cols per block
constexpr int HROW = 1536; // padded row stride for h buffers (multiple of 64)
constexpr int KA   = 1504; // padded activation row stride

// ---------------- static device scratch ----------------
__device__ __align__(128) float g_xz0[(size_t)T * B * 6000];       // interleaved cols
__device__ __align__(128) float g_logits[(size_t)T * B * VOCAB];
__device__ __align__(128) float g_c0[B * HID];
__device__ __align__(128) float g_c1[B * HID];
__device__ __align__(128) float g_nll[T * B];
__device__ __align__(128) float g_b0i[6000];
__device__ __align__(128) float g_b1i[6000];
__device__ __align__(128) __nv_bfloat16 g_inputs[(size_t)T * B * KA];      // padded rows
__device__ __align__(128) __nv_bfloat16 g_W0i[(size_t)(EMB + HID) * 6000]; // gate-interleaved
__device__ __align__(128) __nv_bfloat16 g_W1i[(size_t)2 * HID * 6000];     // gate-interleaved
__device__ __align__(128) __nv_bfloat16 g_swb[(size_t)HID * VOCAB];
__device__ __align__(128) __nv_bfloat16 g_h0[2][B * HROW];  // ping-pong h0
__device__ __align__(128) __nv_bfloat16 g_h1[2][B * HROW];  // ping-pong h1
__device__ __align__(128) __nv_bfloat16 g_out[(size_t)T * B * KA];         // padded rows
__device__ unsigned g_barCount;
__device__ unsigned g_barGen;

__device__ __forceinline__ float sigmoidf_(float x) {
    return 1.0f / (1.0f + expf(-x));
}

// ---------------- fused prep: misc init + ALL weight conversions ----------------
__global__ void prep_all_kernel(const float* __restrict__ b0, const float* __restrict__ b1,
                                const float* __restrict__ W0, const float* __restrict__ W1,
                                const float* __restrict__ sw) {
    constexpr int N0 = (EMB + HID) * 1500;   // W0 (row, unit) pairs
    constexpr int N1 = 2 * HID * 1500;       // W1
    constexpr int N2 = HID * VOCAB / 2;      // sw float2 pairs
    const int i0 = blockIdx.x * blockDim.x + threadIdx.x;

    if (i0 == 0) { g_barCount = 0u; g_barGen = 0u; }
    const __nv_bfloat16 z = __float2bfloat16(0.0f);
    if (i0 < B * HROW) {
        g_h0[0][i0] = z; g_h0[1][i0] = z;
        g_h1[0][i0] = z; g_h1[1][i0] = z;
    }
    if (i0 < B * HID) { g_c0[i0] = 0.0f; g_c1[i0] = 0.0f; }
    if (i0 < T * B * 4) {
        const int r = i0 >> 2, c = i0 & 3;
        g_out[(size_t)r * KA + 1500 + c] = z;
    }
    if (i0 < 6000) {
        const int g = i0 / 1500, j = i0 % 1500;
        g_b0i[4 * j + g] = b0[i0];
        g_b1i[4 * j + g] = b1[i0];
    }

    long long i = i0;
    const long long stride = gridDim.x * (long long)blockDim.x;
    for (; i < (long long)N0 + N1 + N2; i += stride) {
        if (i < N0) {
            const int r = (int)(i / 1500), j = (int)(i % 1500);
            const float* s = W0 + (size_t)r * 6000;
            const __nv_bfloat162 p0 = __floats2bfloat162_rn(s[j], s[1500 + j]);
            const __nv_bfloat162 p1 = __floats2bfloat162_rn(s[3000 + j], s[4500 + j]);
            uint2 pk;
            pk.x = *reinterpret_cast<const uint32_t*>(&p0);
            pk.y = *reinterpret_cast<const uint32_t*>(&p1);
            *reinterpret_cast<uint2*>(g_W0i + (size_t)r * 6000 + 4 * j) = pk;
        } else if (i < (long long)N0 + N1) {
            const int ii = (int)(i - N0);
            const int r = ii / 1500, j = ii % 1500;
            const float* s = W1 + (size_t)r * 6000;
            const __nv_bfloat162 p0 = __floats2bfloat162_rn(s[j], s[1500 + j]);
            const __nv_bfloat162 p1 = __floats2bfloat162_rn(s[3000 + j], s[4500 + j]);
            uint2 pk;
            pk.x = *reinterpret_cast<const uint32_t*>(&p0);
            pk.y = *reinterpret_cast<const uint32_t*>(&p1);
            *reinterpret_cast<uint2*>(g_W1i + (size_t)r * 6000 + 4 * j) = pk;
        } else {
            const int ii = (int)(i - N0 - N1);
            const float2 v = reinterpret_cast<const float2*>(sw)[ii];
            reinterpret_cast<__nv_bfloat162*>(g_swb)[ii] = __floats2bfloat162_rn(v.x, v.y);
        }
    }
}

// embedding gather into padded rows (pad cols zeroed)
__global__ void embed_kernel(const int* __restrict__ x, const float* __restrict__ emb) {
    const int row = blockIdx.x;
    const int tok = x[row];
    const float2* src = reinterpret_cast<const float2*>(emb + (size_t)tok * EMB);
    __nv_bfloat162* dst = reinterpret_cast<__nv_bfloat162*>(g_inputs + (size_t)row * KA);
    for (int i = threadIdx.x; i < KA / 2; i += blockDim.x) {
        if (i < EMB / 2) {
            float2 v = src[i];
            dst[i] = __floats2bfloat162_rn(v.x, v.y);
        } else {
            dst[i] = __floats2bfloat162_rn(0.0f, 0.0f);
        }
    }
}

// ---------------- pipelined bf16 tensor-core GEMM (big batched GEMMs) ----------------
constexpr int GP_PIPE = 3;
constexpr int GP_SMEM = GP_PIPE * (128 * 40 + 32 * 136) * 2;  // 56832 bytes

__global__ void __launch_bounds__(256, 2)
gemm_pipe(const __nv_bfloat16* __restrict__ A, const __nv_bfloat16* __restrict__ Bm,
          float* __restrict__ C, int M, int N, int K,
          int lda, int ldb, int ldc)
{
    extern __shared__ char dynsmem[];
    typedef __nv_bfloat16 (*AsT)[128][40];
    typedef __nv_bfloat16 (*BsT)[32][136];
    AsT As = reinterpret_cast<AsT>(dynsmem);
    BsT Bs = reinterpret_cast<BsT>(dynsmem + GP_PIPE * 128 * 40 * 2);

    const int tid = threadIdx.x;
    const int lane = tid & 31;
    const int warp = tid >> 5;
    const int wm = warp >> 2;
    const int wn = warp & 3;
    const int row0 = blockIdx.y * 128;
    const int col0 = blockIdx.x * 128;
    const int KITER = (K + 31) / 32;

    const int arow = tid >> 2;
    const int acol = (tid & 3) * 8;
    const int brow = tid >> 4;
    const int bcol = (tid & 15) * 8;

    const int lrow = ((lane >> 3) & 1) * 8 + (lane & 7);
    const int lcol = (lane >> 4) * 8;

    float acc[4][4][4];
#pragma unroll
    for (int mt = 0; mt < 4; mt++)
#pragma unroll
        for (int nt = 0; nt < 4; nt++)
#pragma unroll
            for (int r = 0; r < 4; r++) acc[mt][nt][r] = 0.0f;

    auto issue = [&](int it) {
        const int k0 = it * 32;
        const int sb = it % GP_PIPE;
#pragma unroll
        for (int h = 0; h < 2; h++) {
            const int r = arow + h * 64;
            const int gr = row0 + r;
            const int grc = min(gr, M - 1);
            const int bytes = (gr < M) ? 16 : 0;
            uint32_t da = (uint32_t)__cvta_generic_to_shared(&As[sb][r][acol]);
            const void* sa = A + (size_t)grc * lda + k0 + acol;
            asm volatile("cp.async.cg.shared.global [%0], [%1], 16, %2;"
                         :: "r"(da), "l"(sa), "r"(bytes));
        }
#pragma unroll
        for (int h = 0; h < 2; h++) {
            const int r = brow + h * 16;
            const int gk = k0 + r;
            const int gc = col0 + bcol;
            const int bytes = (gk < K && gc < N) ? 16 : 0;
            const int gkc = min(gk, K - 1);
            const int gcc = min(gc, N - 8);
            uint32_t db = (uint32_t)__cvta_generic_to_shared(&Bs[sb][r][bcol]);
            const void* sbp = Bm + (size_t)gkc * ldb + gcc;
            asm volatile("cp.async.cg.shared.global [%0], [%1], 16, %2;"
                         :: "r"(db), "l"(sbp), "r"(bytes));
        }
    };

    issue(0);
    asm volatile("cp.async.commit_group;");
    issue(1);
    asm volatile("cp.async.commit_group;");

#pragma unroll 1
    for (int it = 0; it < KITER; it++) {
        asm volatile("cp.async.wait_group 1;");
        __syncthreads();
        if (it + 2 < KITER) issue(it + 2);
        asm volatile("cp.async.commit_group;");

        const int b = it % GP_PIPE;
#pragma unroll
        for (int ks = 0; ks < 32; ks += 16) {
            uint32_t ar[4][4];
            uint32_t br[2][4];
#pragma unroll
            for (int mt = 0; mt < 4; mt++) {
                uint32_t addr = (uint32_t)__cvta_generic_to_shared(
                    &As[b][wm * 64 + mt * 16 + lrow][ks + lcol]);
                asm volatile("ldmatrix.sync.aligned.m8n8.x4.shared.b16 {%0,%1,%2,%3}, [%4];"
                    : "=r"(ar[mt][0]), "=r"(ar[mt][1]), "=r"(ar[mt][2]), "=r"(ar[mt][3])
                    : "r"(addr));
            }
#pragma unroll
            for (int q = 0; q < 2; q++) {
                uint32_t addr = (uint32_t)__cvta_generic_to_shared(
                    &Bs[b][ks + lrow][wn * 32 + q * 16 + lcol]);
                asm volatile("ldmatrix.sync.aligned.m8n8.x4.trans.shared.b16 {%0,%1,%2,%3}, [%4];"
                    : "=r"(br[q][0]), "=r"(br[q][1]), "=r"(br[q][2]), "=r"(br[q][3])
                    : "r"(addr));
            }
#pragma unroll
            for (int mt = 0; mt < 4; mt++)
#pragma unroll
                for (int nt = 0; nt < 4; nt++) {
                    const int q = nt >> 1;
                    const int p = (nt & 1) * 2;
                    asm volatile(
                        "mma.sync.aligned.m16n8k16.row.col.f32.bf16.bf16.f32 "
                        "{%0,%1,%2,%3}, {%4,%5,%6,%7}, {%8,%9}, {%0,%1,%2,%3};"
                        : "+f"(acc[mt][nt][0]), "+f"(acc[mt][nt][1]),
                          "+f"(acc[mt][nt][2]), "+f"(acc[mt][nt][3])
                        : "r"(ar[mt][0]), "r"(ar[mt][1]), "r"(ar[mt][2]), "r"(ar[mt][3]),
                          "r"(br[q][p]), "r"(br[q][p + 1]));
                }
        }
    }

#pragma unroll
    for (int mt = 0; mt < 4; mt++) {
        const int r0 = row0 + wm * 64 + mt * 16 + (lane >> 2);
#pragma unroll
        for (int nt = 0; nt < 4; nt++) {
            const int c = col0 + wn * 32 + nt * 8 + (lane & 3) * 2;
            if (c < N) {
                if (r0 < M) {
                    C[(long long)r0 * ldc + c]     = acc[mt][nt][0];
                    C[(long long)r0 * ldc + c + 1] = acc[mt][nt][1];
                }
                if (r0 + 8 < M) {
                    C[(long long)(r0 + 8) * ldc + c]     = acc[mt][nt][2];
                    C[(long long)(r0 + 8) * ldc + c + 1] = acc[mt][nt][3];
                }
            }
        }
    }
}

// ---------------- lightweight grid barrier ----------------
__device__ __forceinline__ void grid_barrier(unsigned target) {
    __syncthreads();
    if (threadIdx.x == 0) {
        unsigned a;
        asm volatile("atom.add.release.gpu.u32 %0, [%1], %2;"
                     : "=r"(a) : "l"(&g_barCount), "r"(1u) : "memory");
        if (a == (unsigned)(NBLK - 1)) {
            g_barCount = 0u;
            asm volatile("st.release.gpu.u32 [%0], %1;" :: "l"(&g_barGen), "r"(target) : "memory");
        } else {
            unsigned g;
            do {
                asm volatile("ld.acquire.gpu.u32 %0, [%1];" : "=r"(g) : "l"(&g_barGen) : "memory");
            } while ((int)(g - target) < 0);
        }
    }
    __syncthreads();
}

// ---------------- persistent recurrence ----------------
// R16: warp-private cp.async pipelines. Warp (kg,wn) loads exactly the slices
// it (and its kg-pair partner) consume; the 48 per-iteration __syncthreads are
// replaced by named PAIR barriers (bar.sync 1+kg, 64). K-merge reduced to 2
// staged rounds using two zs copies (both aliased onto the As stage buffers).
constexpr int RC_PIPE = 3;
constexpr int WPS = 56;   // Wp row stride (elems): 112 B, 16B-aligned, degree-2
struct RcSmem {
    __nv_bfloat16 Wp[1536][WPS];          // 172032 B persistent W0h cols
    __nv_bfloat16 As[RC_PIPE][64][72];    // 27648 B (zsA+zsB alias this region)
    __nv_bfloat16 Bs1[RC_PIPE][64][56];   // 21504 B
};
constexpr int RC_SMEM = sizeof(RcSmem);   // 221184 bytes

__global__ void __launch_bounds__(256, 1) recurrence_kernel() {
    extern __shared__ char dynsmem[];
    RcSmem* S = reinterpret_cast<RcSmem*>(dynsmem);
    // zsA/zsB alias the As stage buffers (2 x 13312 B <= 27648 B); epilogue-only.
    typedef float (*ZsT)[52];
    ZsT zsA = reinterpret_cast<ZsT>(&S->As[0][0][0]);
    ZsT zsB = zsA + 64;

    const int tid = threadIdx.x;
    const int lane = tid & 31;
    const int warp = tid >> 5;
    const int kg = warp >> 1;        // 0..3  K-group (pair id)
    const int wn = warp & 1;         // 0..1  N-half
    const int col0 = blockIdx.x * CPB;
    const int lrow = ((lane >> 3) & 1) * 8 + (lane & 7);
    const int lcol = (lane >> 4) * 8;
    const int x2row = lane & 15;

    const __nv_bfloat16* W0h = g_W0i + (size_t)EMB * 6000;

    // -------- load persistent W0h block columns into smem (stride WPS) --------
    {
        for (int slot = tid; slot < 36 * 6; slot += 256) {
            const int row = 1500 + slot / 6, v = slot % 6;
            *reinterpret_cast<uint4*>(&S->Wp[row][v * 8]) = make_uint4(0u, 0u, 0u, 0u);
        }
        for (int idx = tid; idx < 1500 * 6; idx += 256) {
            const int row = idx / 6, v = idx % 6;
            uint32_t d = (uint32_t)__cvta_generic_to_shared(&S->Wp[row][v * 8]);
            const void* s = W0h + (size_t)row * 6000 + col0 + v * 8;
            asm volatile("cp.async.cg.shared.global [%0], [%1], 16;" :: "r"(d), "l"(s));
        }
        asm volatile("cp.async.commit_group;");
        asm volatile("cp.async.wait_group 0;");
    }

    // -------- bootstrap: gates0(0) from xz0(0)+b0 (h(-1)=0, c=0) --------
#pragma unroll
    for (int i = 0; i < 3; i++) {
        const int ul = i * 256 + tid;
        const int bb = ul / 12;
        const int u  = ul % 12;
        const int gc = col0 + 4 * u;
        const float4 xz = *reinterpret_cast<const float4*>(&g_xz0[(size_t)bb * 6000 + gc]);
        const float4 b4v = *reinterpret_cast<const float4*>(&g_b0i[gc]);
        const float zi = xz.x + b4v.x, zj = xz.y + b4v.y;
        const float zo = xz.w + b4v.w;
        const float cn = sigmoidf_(zi) * tanhf(zj);
        const int ju = blockIdx.x * 12 + u;
        g_c0[bb * HID + ju] = cn;
        g_h0[0][bb * HROW + ju] = __float2bfloat16(tanhf(cn) * sigmoidf_(zo));
    }
    unsigned gen = 1;
    grid_barrier(gen);

#pragma unroll 1
    for (int t = 0; t < T; t++) {
        const int p = t & 1;
        const __nv_bfloat16* Ah0 = g_h0[p];        // h0(t)
        const __nv_bfloat16* Ah1 = g_h1[1 - p];    // h1(t-1)
        const __nv_bfloat16* W1a = g_W1i;
        const __nv_bfloat16* W1b = g_W1i + (size_t)1500 * 6000;

        // warp-private loader: warp (kg,wn) loads
        //   A: rows [wn*32, wn*32+32) x cols [kg*16, +16)  (pair covers all 64 rows)
        //   B: rows [kg*16, +16) of chunk x cols [wn*24, +24)
        auto issue = [&](int it) {
            const bool s1 = (it >= 24);
            const __nv_bfloat16* Ab = s1 ? Ah1 : Ah0;
            const __nv_bfloat16* Wb1 = s1 ? W1b : W1a;
            const int kk = (s1 ? (it - 24) : it) * 64;
            const int sb = it % RC_PIPE;
#pragma unroll
            for (int i = 0; i < 2; i++) {
                const int slot = lane + i * 32;      // 0..63
                const int row = wn * 32 + (slot >> 1);
                const int cv = kg * 16 + (slot & 1) * 8;
                uint32_t da = (uint32_t)__cvta_generic_to_shared(&S->As[sb][row][cv]);
                const void* sa = Ab + (size_t)row * HROW + kk + cv;
                asm volatile("cp.async.cg.shared.global [%0], [%1], 16;" :: "r"(da), "l"(sa));
            }
#pragma unroll
            for (int i = 0; i < 2; i++) {
                const int slot = lane + i * 32;
                if (slot < 48) {
                    const int row = slot / 3, v = slot % 3;
                    int krow = kk + kg * 16 + row;
                    const int bytes = (krow < 1500) ? 16 : 0;
                    if (krow >= 1500) krow = 0;
                    uint32_t db1 = (uint32_t)__cvta_generic_to_shared(
                        &S->Bs1[sb][kg * 16 + row][wn * 24 + v * 8]);
                    const void* sb1 = Wb1 + (size_t)krow * 6000 + col0 + wn * 24 + v * 8;
                    asm volatile("cp.async.cg.shared.global [%0], [%1], 16, %2;"
                                 :: "r"(db1), "l"(sb1), "r"(bytes));
                }
            }
        };

        float accA[4][3][4], accB[4][3][4];
#pragma unroll
        for (int mt = 0; mt < 4; mt++)
#pragma unroll
            for (int nt = 0; nt < 3; nt++)
#pragma unroll
                for (int r = 0; r < 4; r++) { accA[mt][nt][r] = 0.0f; accB[mt][nt][r] = 0.0f; }

        issue(0);
        asm volatile("cp.async.commit_group;");
        issue(1);
        asm volatile("cp.async.commit_group;");

        const int ks = kg * 16;
        const int barid = 1 + kg;

#define MMA_(ACC, AT, R0, R1)                                                    \
    asm volatile("mma.sync.aligned.m16n8k16.row.col.f32.bf16.bf16.f32 "          \
                 "{%0,%1,%2,%3}, {%4,%5,%6,%7}, {%8,%9}, {%0,%1,%2,%3};"         \
                 : "+f"(ACC[0]), "+f"(ACC[1]), "+f"(ACC[2]), "+f"(ACC[3])        \
                 : "r"(AT[0]), "r"(AT[1]), "r"(AT[2]), "r"(AT[3]), "r"(R0), "r"(R1))

        // ---- segment 1: A=h0(t); accA from persistent Wp, accB from Bs1 ----
#pragma unroll 1
        for (int it = 0; it < 24; it++) {
            asm volatile("cp.async.wait_group 1;");
            asm volatile("bar.sync %0, 64;" :: "r"(barid) : "memory");
            issue(it + 2);
            asm volatile("cp.async.commit_group;");

            const int b = it % RC_PIPE;
            const int kk = it * 64;
            uint32_t a4[4][4];
#pragma unroll
            for (int mt = 0; mt < 4; mt++) {
                uint32_t addr = (uint32_t)__cvta_generic_to_shared(
                    &S->As[b][mt * 16 + lrow][ks + lcol]);
                asm volatile("ldmatrix.sync.aligned.m8n8.x4.shared.b16 {%0,%1,%2,%3}, [%4];"
                    : "=r"(a4[mt][0]), "=r"(a4[mt][1]), "=r"(a4[mt][2]), "=r"(a4[mt][3])
                    : "r"(addr));
            }
            uint32_t b0q[4], b0d[2], b1q[4], b1d[2];
            {
                uint32_t addr = (uint32_t)__cvta_generic_to_shared(
                    &S->Wp[kk + ks + lrow][wn * 24 + lcol]);
                asm volatile("ldmatrix.sync.aligned.m8n8.x4.trans.shared.b16 {%0,%1,%2,%3}, [%4];"
                    : "=r"(b0q[0]), "=r"(b0q[1]), "=r"(b0q[2]), "=r"(b0q[3]) : "r"(addr));
                uint32_t addr2 = (uint32_t)__cvta_generic_to_shared(
                    &S->Wp[kk + ks + x2row][wn * 24 + 16]);
                asm volatile("ldmatrix.sync.aligned.m8n8.x2.trans.shared.b16 {%0,%1}, [%2];"
                    : "=r"(b0d[0]), "=r"(b0d[1]) : "r"(addr2));
            }
            {
                uint32_t addr = (uint32_t)__cvta_generic_to_shared(
                    &S->Bs1[b][ks + lrow][wn * 24 + lcol]);
                asm volatile("ldmatrix.sync.aligned.m8n8.x4.trans.shared.b16 {%0,%1,%2,%3}, [%4];"
                    : "=r"(b1q[0]), "=r"(b1q[1]), "=r"(b1q[2]), "=r"(b1q[3]) : "r"(addr));
                uint32_t addr2 = (uint32_t)__cvta_generic_to_shared(
                    &S->Bs1[b][ks + x2row][wn * 24 + 16]);
                asm volatile("ldmatrix.sync.aligned.m8n8.x2.trans.shared.b16 {%0,%1}, [%2];"
                    : "=r"(b1d[0]), "=r"(b1d[1]) : "r"(addr2));
            }
#pragma unroll
            for (int mt = 0; mt < 4; mt++) {
                MMA_(accA[mt][0], a4[mt], b0q[0], b0q[1]);
                MMA_(accA[mt][1], a4[mt], b0q[2], b0q[3]);
                MMA_(accA[mt][2], a4[mt], b0d[0], b0d[1]);
                MMA_(accB[mt][0], a4[mt], b1q[0], b1q[1]);
                MMA_(accB[mt][1], a4[mt], b1q[2], b1q[3]);
                MMA_(accB[mt][2], a4[mt], b1d[0], b1d[1]);
            }
        }

        // ---- segment 2: A=h1(t-1), Bs1->accB, 24 iters ----
#pragma unroll 1
        for (int it = 24; it < 48; it++) {
            asm volatile("cp.async.wait_group 1;");
            asm volatile("bar.sync %0, 64;" :: "r"(barid) : "memory");
            if (it + 2 < 48) issue(it + 2);
            asm volatile("cp.async.commit_group;");

            const int b = it % RC_PIPE;
            uint32_t a4[4][4];
#pragma unroll
            for (int mt = 0; mt < 4; mt++) {
                uint32_t addr = (uint32_t)__cvta_generic_to_shared(
                    &S->As[b][mt * 16 + lrow][ks + lcol]);
                asm volatile("ldmatrix.sync.aligned.m8n8.x4.shared.b16 {%0,%1,%2,%3}, [%4];"
                    : "=r"(a4[mt][0]), "=r"(a4[mt][1]), "=r"(a4[mt][2]), "=r"(a4[mt][3])
                    : "r"(addr));
            }
            uint32_t b1q[4], b1d[2];
            {
                uint32_t addr = (uint32_t)__cvta_generic_to_shared(
                    &S->Bs1[b][ks + lrow][wn * 24 + lcol]);
                asm volatile("ldmatrix.sync.aligned.m8n8.x4.trans.shared.b16 {%0,%1,%2,%3}, [%4];"
                    : "=r"(b1q[0]), "=r"(b1q[1]), "=r"(b1q[2]), "=r"(b1q[3]) : "r"(addr));
                uint32_t addr2 = (uint32_t)__cvta_generic_to_shared(
                    &S->Bs1[b][ks + x2row][wn * 24 + 16]);
                asm volatile("ldmatrix.sync.aligned.m8n8.x2.trans.shared.b16 {%0,%1}, [%2];"
                    : "=r"(b1d[0]), "=r"(b1d[1]) : "r"(addr2));
            }
#pragma unroll
            for (int mt = 0; mt < 4; mt++) {
                MMA_(accB[mt][0], a4[mt], b1q[0], b1q[1]);
                MMA_(accB[mt][1], a4[mt], b1q[2], b1q[3]);
                MMA_(accB[mt][2], a4[mt], b1d[0], b1d[1]);
            }
        }
#undef MMA_

        // drain all cp.async groups before zsA/zsB alias As
        asm volatile("cp.async.wait_group 0;");

        const int r0m = lane >> 2;
        const int cbm = wn * 24 + (lane & 3) * 2;

        // ---- 2-round merge of accB, then gates1(t) ----
        __syncthreads();
        if (kg == 0 || kg == 2) {
            ZsT zz = (kg == 0) ? zsA : zsB;
#pragma unroll
            for (int mt = 0; mt < 4; mt++) {
                const int rr = mt * 16 + r0m;
#pragma unroll
                for (int nt = 0; nt < 3; nt++) {
                    const int cc = cbm + nt * 8;
                    zz[rr][cc]     = accB[mt][nt][0];
                    zz[rr][cc + 1] = accB[mt][nt][1];
                    zz[rr + 8][cc]     = accB[mt][nt][2];
                    zz[rr + 8][cc + 1] = accB[mt][nt][3];
                }
            }
        }
        __syncthreads();
        if (kg == 1 || kg == 3) {
            ZsT zz = (kg == 1) ? zsA : zsB;
#pragma unroll
            for (int mt = 0; mt < 4; mt++) {
                const int rr = mt * 16 + r0m;
#pragma unroll
                for (int nt = 0; nt < 3; nt++) {
                    const int cc = cbm + nt * 8;
                    zz[rr][cc]     += accB[mt][nt][0];
                    zz[rr][cc + 1] += accB[mt][nt][1];
                    zz[rr + 8][cc]     += accB[mt][nt][2];
                    zz[rr + 8][cc + 1] += accB[mt][nt][3];
                }
            }
        }
        __syncthreads();
#pragma unroll
        for (int i = 0; i < 3; i++) {
            const int ul = i * 256 + tid;
            const int bb = ul / 12;
            const int u  = ul % 12;
            const float4 zA = *reinterpret_cast<const float4*>(&zsA[bb][4 * u]);
            const float4 zB = *reinterpret_cast<const float4*>(&zsB[bb][4 * u]);
            const int gc = col0 + 4 * u;
            const float4 b4v = *reinterpret_cast<const float4*>(&g_b1i[gc]);
            const float zi = zA.x + zB.x + b4v.x, zj = zA.y + zB.y + b4v.y;
            const float zf = zA.z + zB.z + b4v.z, zo = zA.w + zB.w + b4v.w;
            const int ju = blockIdx.x * 12 + u;
            const float c = g_c1[bb * HID + ju];
            const float cn = c * sigmoidf_(zf + FORGET_BIAS) + sigmoidf_(zi) * tanhf(zj);
            g_c1[bb * HID + ju] = cn;
            const float h = tanhf(cn) * sigmoidf_(zo);
            const __nv_bfloat16 hb = __float2bfloat16(h);
            g_h1[p][bb * HROW + ju] = hb;
            g_out[(size_t)(t * B + bb) * KA + ju] = hb;
        }

        // ---- 2-round merge of accA, then gates0(t+1) ----
        if (t < T - 1) {
            __syncthreads();
            if (kg == 0 || kg == 2) {
                ZsT zz = (kg == 0) ? zsA : zsB;
#pragma unroll
                for (int mt = 0; mt < 4; mt++) {
                    const int rr = mt * 16 + r0m;
#pragma unroll
                    for (int nt = 0; nt < 3; nt++) {
                        const int cc = cbm + nt * 8;
                        zz[rr][cc]     = accA[mt][nt][0];
                        zz[rr][cc + 1] = accA[mt][nt][1];
                        zz[rr + 8][cc]     = accA[mt][nt][2];
                        zz[rr + 8][cc + 1] = accA[mt][nt][3];
                    }
                }
            }
            __syncthreads();
            if (kg == 1 || kg == 3) {
                ZsT zz = (kg == 1) ? zsA : zsB;
#pragma unroll
                for (int mt = 0; mt < 4; mt++) {
                    const int rr = mt * 16 + r0m;
#pragma unroll
                    for (int nt = 0; nt < 3; nt++) {
                        const int cc = cbm + nt * 8;
                        zz[rr][cc]     += accA[mt][nt][0];
                        zz[rr][cc + 1] += accA[mt][nt][1];
                        zz[rr + 8][cc]     += accA[mt][nt][2];
                        zz[rr + 8][cc + 1] += accA[mt][nt][3];
                    }
                }
            }
            __syncthreads();
#pragma unroll
            for (int i = 0; i < 3; i++) {
                const int ul = i * 256 + tid;
                const int bb = ul / 12;
                const int u  = ul % 12;
                const float4 zA = *reinterpret_cast<const float4*>(&zsA[bb][4 * u]);
                const float4 zB = *reinterpret_cast<const float4*>(&zsB[bb][4 * u]);
                const int gc = col0 + 4 * u;
                const float4 b4v = *reinterpret_cast<const float4*>(&g_b0i[gc]);
                const float4 xz = *reinterpret_cast<const float4*>(
                    &g_xz0[(size_t)((t + 1) * B + bb) * 6000 + gc]);
                const float zi = zA.x + zB.x + b4v.x + xz.x;
                const float zj = zA.y + zB.y + b4v.y + xz.y;
                const float zf = zA.z + zB.z + b4v.z + xz.z;
                const float zo = zA.w + zB.w + b4v.w + xz.w;
                const int ju = blockIdx.x * 12 + u;
                const float c = g_c0[bb * HID + ju];
                const float cn = c * sigmoidf_(zf + FORGET_BIAS) + sigmoidf_(zi) * tanhf(zj);
                g_c0[bb * HID + ju] = cn;
                const float h = tanhf(cn) * sigmoidf_(zo);
                g_h0[1 - p][bb * HROW + ju] = __float2bfloat16(h);
            }
        }

        gen++;
        grid_barrier(gen);
    }
}

// ---------------- log-softmax + NLL per row ----------------
__global__ void row_nll_kernel(const float* __restrict__ sb, const int* __restrict__ y) {
    __shared__ float red[256];
    const int row = blockIdx.x;
    const float* lr = g_logits + (size_t)row * VOCAB;
    float m = -1e30f;
    for (int v = threadIdx.x; v < VOCAB; v += 256) m = fmaxf(m, lr[v] + sb[v]);
    red[threadIdx.x] = m; __syncthreads();
    for (int s = 128; s > 0; s >>= 1) {
        if (threadIdx.x < s) red[threadIdx.x] = fmaxf(red[threadIdx.x], red[threadIdx.x + s]);
        __syncthreads();
    }
    m = red[0]; __syncthreads();
    float sum = 0.0f;
    for (int v = threadIdx.x; v < VOCAB; v += 256) sum += expf(lr[v] + sb[v] - m);
    red[threadIdx.x] = sum; __syncthreads();
    for (int s = 128; s > 0; s >>= 1) {
        if (threadIdx.x < s) red[threadIdx.x] += red[threadIdx.x + s];
        __syncthreads();
    }
    if (threadIdx.x == 0) {
        const int tgt = y[row];
        g_nll[row] = m + logf(red[0]) - (lr[tgt] + sb[tgt]);
    }
}

__global__ void final_loss_kernel(float* __restrict__ out) {
    __shared__ float red[256];
    float s = 0.0f;
    for (int i = threadIdx.x; i < T * B; i += 256) s += g_nll[i];
    red[threadIdx.x] = s; __syncthreads();
    for (int st = 128; st > 0; st >>= 1) {
        if (threadIdx.x < st) red[threadIdx.x] += red[threadIdx.x + st];
        __syncthreads();
    }
    if (threadIdx.x == 0) out[0] = red[0] / (float)B;
}

// ---------------- launch ----------------
extern "C" void kernel_launch(void* const* d_in, const int* in_sizes, int n_in,
                              void* d_out, int out_size) {
    const int*   x   = (const int*)d_in[0];
    const int*   y   = (const int*)d_in[1];
    const float* emb = (const float*)d_in[2];
    const float* W0  = (const float*)d_in[3];
    const float* b0  = (const float*)d_in[4];
    const float* W1  = (const float*)d_in[5];
    const float* b1  = (const float*)d_in[6];
    const float* sw  = (const float*)d_in[7];
    const float* sb  = (const float*)d_in[8];
    float* out = (float*)d_out;

    void *pW0i, *pSwb, *pInputs, *pOutB, *pXz0, *pLogits;
    cudaGetSymbolAddress(&pW0i, g_W0i);
    cudaGetSymbolAddress(&pSwb, g_swb);
    cudaGetSymbolAddress(&pInputs, g_inputs);
    cudaGetSymbolAddress(&pOutB, g_out);
    cudaGetSymbolAddress(&pXz0, g_xz0);
    cudaGetSymbolAddress(&pLogits, g_logits);

    static bool attrDone = false;
    if (!attrDone) {
        cudaFuncSetAttribute(gemm_pipe, cudaFuncAttributeMaxDynamicSharedMemorySize, GP_SMEM);
        cudaFuncSetAttribute(recurrence_kernel, cudaFuncAttributeMaxDynamicSharedMemorySize, RC_SMEM);
        attrDone = true;
    }

    // (1) fused prep (misc init + all weight conversions)  (2) embedding
    prep_all_kernel<<<2048, 256>>>(b0, b1, W0, W1, sw);
    embed_kernel<<<T * B, 128>>>(x, emb);

    // (3) prefix: xz0 = inputs @ W0i[0:EMB,:]  M=2240, N=6000, K=1500
    {
        dim3 grid((6000 + 127) / 128, (T * B + 127) / 128, 1);
        gemm_pipe<<<grid, 256, GP_SMEM>>>(
            (const __nv_bfloat16*)pInputs, (const __nv_bfloat16*)pW0i, (float*)pXz0,
            T * B, 6000, EMB, KA, 6000, 6000);
    }

    // (4) full recurrence (warp-private pipelines + pair barriers + 2-round merge)
    recurrence_kernel<<<NBLK, 256, RC_SMEM>>>();

    // (5) logits = outputs @ softmax_w   M=2240, N=10000, K=1500
    {
        dim3 grid((VOCAB + 127) / 128, (T * B + 127) / 128, 1);
        gemm_pipe<<<grid, 256, GP_SMEM>>>(
            (const __nv_bfloat16*)pOutB, (const __nv_bfloat16*)pSwb, (float*)pLogits,
            T * B, VOCAB, HID, KA, VOCAB, VOCAB);
    }

    // (6,7) per-row log-softmax NLL + deterministic final reduction
    row_nll_kernel<<<T * B, 256>>>(sb, y);
    final_loss_kernel<<<1, 256>>>(out);
}

// round 17
// speedup vs baseline: 1.2850x; 1.0103x over previous
#include <cuda_runtime.h>
#include <cuda_bf16.h>
#include <math.h>
#include <stdint.h>

// Problem constants
constexpr int VOCAB = 10000;
constexpr int EMB   = 1500;
constexpr int HID   = 1500;
constexpr int T     = 35;
constexpr int B     = 64;
constexpr float FORGET_BIAS = 1.0f;

// Recurrence partitioning: 6000 gate cols = 125 blocks * 48 cols (12 hidden units * 4 gates)
constexpr int NBLK = 125;
constexpr int CPB  = 48;   // cols per block
constexpr int HROW = 1536; // padded row stride for h buffers (multiple of 64)
constexpr int KA   = 1504; // padded activation row stride

// ---------------- static device scratch ----------------
__device__ __align__(128) float g_xz0[(size_t)T * B * 6000];       // interleaved cols
__device__ __align__(128) float g_logits[(size_t)T * B * VOCAB];
__device__ __align__(128) float g_c0[B * HID];
__device__ __align__(128) float g_c1[B * HID];
__device__ __align__(128) float g_nll[T * B];
__device__ __align__(128) float g_b0i[6000];
__device__ __align__(128) float g_b1i[6000];
__device__ __align__(128) __nv_bfloat16 g_inputs[(size_t)T * B * KA];      // padded rows
__device__ __align__(128) __nv_bfloat16 g_W0i[(size_t)(EMB + HID) * 6000]; // gate-interleaved
__device__ __align__(128) __nv_bfloat16 g_W1i[(size_t)2 * HID * 6000];     // gate-interleaved
__device__ __align__(128) __nv_bfloat16 g_swb[(size_t)HID * VOCAB];
__device__ __align__(128) __nv_bfloat16 g_h0[2][B * HROW];  // ping-pong h0
__device__ __align__(128) __nv_bfloat16 g_h1[2][B * HROW];  // ping-pong h1
__device__ __align__(128) __nv_bfloat16 g_out[(size_t)T * B * KA];         // padded rows
__device__ unsigned g_barCount;
__device__ unsigned g_barGen;

__device__ __forceinline__ float sigmoidf_(float x) {
    return 1.0f / (1.0f + expf(-x));
}

// ---------------- fused prep: misc init + ALL weight conversions ----------------
__global__ void prep_all_kernel(const float* __restrict__ b0, const float* __restrict__ b1,
                                const float* __restrict__ W0, const float* __restrict__ W1,
                                const float* __restrict__ sw) {
    constexpr int N0 = (EMB + HID) * 1500;   // W0 (row, unit) pairs
    constexpr int N1 = 2 * HID * 1500;       // W1
    constexpr int N2 = HID * VOCAB / 2;      // sw float2 pairs
    const int i0 = blockIdx.x * blockDim.x + threadIdx.x;

    if (i0 == 0) { g_barCount = 0u; g_barGen = 0u; }
    const __nv_bfloat16 z = __float2bfloat16(0.0f);
    if (i0 < B * HROW) {
        g_h0[0][i0] = z; g_h0[1][i0] = z;
        g_h1[0][i0] = z; g_h1[1][i0] = z;
    }
    if (i0 < B * HID) { g_c0[i0] = 0.0f; g_c1[i0] = 0.0f; }
    if (i0 < T * B * 4) {
        const int r = i0 >> 2, c = i0 & 3;
        g_out[(size_t)r * KA + 1500 + c] = z;
    }
    if (i0 < 6000) {
        const int g = i0 / 1500, j = i0 % 1500;
        g_b0i[4 * j + g] = b0[i0];
        g_b1i[4 * j + g] = b1[i0];
    }

    long long i = i0;
    const long long stride = gridDim.x * (long long)blockDim.x;
    for (; i < (long long)N0 + N1 + N2; i += stride) {
        if (i < N0) {
            const int r = (int)(i / 1500), j = (int)(i % 1500);
            const float* s = W0 + (size_t)r * 6000;
            const __nv_bfloat162 p0 = __floats2bfloat162_rn(s[j], s[1500 + j]);
            const __nv_bfloat162 p1 = __floats2bfloat162_rn(s[3000 + j], s[4500 + j]);
            uint2 pk;
            pk.x = *reinterpret_cast<const uint32_t*>(&p0);
            pk.y = *reinterpret_cast<const uint32_t*>(&p1);
            *reinterpret_cast<uint2*>(g_W0i + (size_t)r * 6000 + 4 * j) = pk;
        } else if (i < (long long)N0 + N1) {
            const int ii = (int)(i - N0);
            const int r = ii / 1500, j = ii % 1500;
            const float* s = W1 + (size_t)r * 6000;
            const __nv_bfloat162 p0 = __floats2bfloat162_rn(s[j], s[1500 + j]);
            const __nv_bfloat162 p1 = __floats2bfloat162_rn(s[3000 + j], s[4500 + j]);
            uint2 pk;
            pk.x = *reinterpret_cast<const uint32_t*>(&p0);
            pk.y = *reinterpret_cast<const uint32_t*>(&p1);
            *reinterpret_cast<uint2*>(g_W1i + (size_t)r * 6000 + 4 * j) = pk;
        } else {
            const int ii = (int)(i - N0 - N1);
            const float2 v = reinterpret_cast<const float2*>(sw)[ii];
            reinterpret_cast<__nv_bfloat162*>(g_swb)[ii] = __floats2bfloat162_rn(v.x, v.y);
        }
    }
}

// embedding gather into padded rows (pad cols zeroed)
__global__ void embed_kernel(const int* __restrict__ x, const float* __restrict__ emb) {
    const int row = blockIdx.x;
    const int tok = x[row];
    const float2* src = reinterpret_cast<const float2*>(emb + (size_t)tok * EMB);
    __nv_bfloat162* dst = reinterpret_cast<__nv_bfloat162*>(g_inputs + (size_t)row * KA);
    for (int i = threadIdx.x; i < KA / 2; i += blockDim.x) {
        if (i < EMB / 2) {
            float2 v = src[i];
            dst[i] = __floats2bfloat162_rn(v.x, v.y);
        } else {
            dst[i] = __floats2bfloat162_rn(0.0f, 0.0f);
        }
    }
}

// ---------------- pipelined bf16 tensor-core GEMM (big batched GEMMs) ----------------
constexpr int GP_PIPE = 3;
constexpr int GP_SMEM = GP_PIPE * (128 * 40 + 32 * 136) * 2;  // 56832 bytes

__global__ void __launch_bounds__(256, 2)
gemm_pipe(const __nv_bfloat16* __restrict__ A, const __nv_bfloat16* __restrict__ Bm,
          float* __restrict__ C, int M, int N, int K,
          int lda, int ldb, int ldc)
{
    extern __shared__ char dynsmem[];
    typedef __nv_bfloat16 (*AsT)[128][40];
    typedef __nv_bfloat16 (*BsT)[32][136];
    AsT As = reinterpret_cast<AsT>(dynsmem);
    BsT Bs = reinterpret_cast<BsT>(dynsmem + GP_PIPE * 128 * 40 * 2);

    const int tid = threadIdx.x;
    const int lane = tid & 31;
    const int warp = tid >> 5;
    const int wm = warp >> 2;
    const int wn = warp & 3;
    const int row0 = blockIdx.y * 128;
    const int col0 = blockIdx.x * 128;
    const int KITER = (K + 31) / 32;

    const int arow = tid >> 2;
    const int acol = (tid & 3) * 8;
    const int brow = tid >> 4;
    const int bcol = (tid & 15) * 8;

    const int lrow = ((lane >> 3) & 1) * 8 + (lane & 7);
    const int lcol = (lane >> 4) * 8;

    float acc[4][4][4];
#pragma unroll
    for (int mt = 0; mt < 4; mt++)
#pragma unroll
        for (int nt = 0; nt < 4; nt++)
#pragma unroll
            for (int r = 0; r < 4; r++) acc[mt][nt][r] = 0.0f;

    auto issue = [&](int it) {
        const int k0 = it * 32;
        const int sb = it % GP_PIPE;
#pragma unroll
        for (int h = 0; h < 2; h++) {
            const int r = arow + h * 64;
            const int gr = row0 + r;
            const int grc = min(gr, M - 1);
            const int bytes = (gr < M) ? 16 : 0;
            uint32_t da = (uint32_t)__cvta_generic_to_shared(&As[sb][r][acol]);
            const void* sa = A + (size_t)grc * lda + k0 + acol;
            asm volatile("cp.async.cg.shared.global [%0], [%1], 16, %2;"
                         :: "r"(da), "l"(sa), "r"(bytes));
        }
#pragma unroll
        for (int h = 0; h < 2; h++) {
            const int r = brow + h * 16;
            const int gk = k0 + r;
            const int gc = col0 + bcol;
            const int bytes = (gk < K && gc < N) ? 16 : 0;
            const int gkc = min(gk, K - 1);
            const int gcc = min(gc, N - 8);
            uint32_t db = (uint32_t)__cvta_generic_to_shared(&Bs[sb][r][bcol]);
            const void* sbp = Bm + (size_t)gkc * ldb + gcc;
            asm volatile("cp.async.cg.shared.global [%0], [%1], 16, %2;"
                         :: "r"(db), "l"(sbp), "r"(bytes));
        }
    };

    issue(0);
    asm volatile("cp.async.commit_group;");
    issue(1);
    asm volatile("cp.async.commit_group;");

#pragma unroll 1
    for (int it = 0; it < KITER; it++) {
        asm volatile("cp.async.wait_group 1;");
        __syncthreads();
        if (it + 2 < KITER) issue(it + 2);
        asm volatile("cp.async.commit_group;");

        const int b = it % GP_PIPE;
#pragma unroll
        for (int ks = 0; ks < 32; ks += 16) {
            uint32_t ar[4][4];
            uint32_t br[2][4];
#pragma unroll
            for (int mt = 0; mt < 4; mt++) {
                uint32_t addr = (uint32_t)__cvta_generic_to_shared(
                    &As[b][wm * 64 + mt * 16 + lrow][ks + lcol]);
                asm volatile("ldmatrix.sync.aligned.m8n8.x4.shared.b16 {%0,%1,%2,%3}, [%4];"
                    : "=r"(ar[mt][0]), "=r"(ar[mt][1]), "=r"(ar[mt][2]), "=r"(ar[mt][3])
                    : "r"(addr));
            }
#pragma unroll
            for (int q = 0; q < 2; q++) {
                uint32_t addr = (uint32_t)__cvta_generic_to_shared(
                    &Bs[b][ks + lrow][wn * 32 + q * 16 + lcol]);
                asm volatile("ldmatrix.sync.aligned.m8n8.x4.trans.shared.b16 {%0,%1,%2,%3}, [%4];"
                    : "=r"(br[q][0]), "=r"(br[q][1]), "=r"(br[q][2]), "=r"(br[q][3])
                    : "r"(addr));
            }
#pragma unroll
            for (int mt = 0; mt < 4; mt++)
#pragma unroll
                for (int nt = 0; nt < 4; nt++) {
                    const int q = nt >> 1;
                    const int p = (nt & 1) * 2;
                    asm volatile(
                        "mma.sync.aligned.m16n8k16.row.col.f32.bf16.bf16.f32 "
                        "{%0,%1,%2,%3}, {%4,%5,%6,%7}, {%8,%9}, {%0,%1,%2,%3};"
                        : "+f"(acc[mt][nt][0]), "+f"(acc[mt][nt][1]),
                          "+f"(acc[mt][nt][2]), "+f"(acc[mt][nt][3])
                        : "r"(ar[mt][0]), "r"(ar[mt][1]), "r"(ar[mt][2]), "r"(ar[mt][3]),
                          "r"(br[q][p]), "r"(br[q][p + 1]));
                }
        }
    }

#pragma unroll
    for (int mt = 0; mt < 4; mt++) {
        const int r0 = row0 + wm * 64 + mt * 16 + (lane >> 2);
#pragma unroll
        for (int nt = 0; nt < 4; nt++) {
            const int c = col0 + wn * 32 + nt * 8 + (lane & 3) * 2;
            if (c < N) {
                if (r0 < M) {
                    C[(long long)r0 * ldc + c]     = acc[mt][nt][0];
                    C[(long long)r0 * ldc + c + 1] = acc[mt][nt][1];
                }
                if (r0 + 8 < M) {
                    C[(long long)(r0 + 8) * ldc + c]     = acc[mt][nt][2];
                    C[(long long)(r0 + 8) * ldc + c + 1] = acc[mt][nt][3];
                }
            }
        }
    }
}

// ---------------- lightweight grid barrier ----------------
__device__ __forceinline__ void grid_barrier(unsigned target) {
    __syncthreads();
    if (threadIdx.x == 0) {
        unsigned a;
        asm volatile("atom.add.release.gpu.u32 %0, [%1], %2;"
                     : "=r"(a) : "l"(&g_barCount), "r"(1u) : "memory");
        if (a == (unsigned)(NBLK - 1)) {
            g_barCount = 0u;
            asm volatile("st.release.gpu.u32 [%0], %1;" :: "l"(&g_barGen), "r"(target) : "memory");
        } else {
            unsigned g;
            do {
                asm volatile("ld.acquire.gpu.u32 %0, [%1];" : "=r"(g) : "l"(&g_barGen) : "memory");
            } while ((int)(g - target) < 0);
        }
    }
    __syncthreads();
}

// ---------------- persistent recurrence ----------------
// R17: 512 threads (16 warps) for latency hiding — occupancy was the binder
// (occ 12.5%, issue 20.7%, no pipe saturated). Warp layout kg(4) x wn(2) x wm(2):
// each warp does 2 m16-frags x 24 N-cols on its 16-wide K slice. Per-kg named
// barriers (128 threads). 2-round K-merge as R16.
constexpr int RC_PIPE = 3;
constexpr int WPS = 56;   // Wp row stride (elems): 112 B, 16B-aligned, degree-2
struct RcSmem {
    __nv_bfloat16 Wp[1536][WPS];          // 172032 B persistent W0h cols
    __nv_bfloat16 As[RC_PIPE][64][72];    // 27648 B (zsA+zsB alias this region)
    __nv_bfloat16 Bs1[RC_PIPE][64][56];   // 21504 B
};
constexpr int RC_SMEM = sizeof(RcSmem);   // 221184 bytes

__global__ void __launch_bounds__(512, 1) recurrence_kernel() {
    extern __shared__ char dynsmem[];
    RcSmem* S = reinterpret_cast<RcSmem*>(dynsmem);
    typedef float (*ZsT)[52];
    ZsT zsA = reinterpret_cast<ZsT>(&S->As[0][0][0]);
    ZsT zsB = zsA + 64;

    const int tid = threadIdx.x;
    const int lane = tid & 31;
    const int warp = tid >> 5;       // 0..15
    const int kg = warp >> 2;        // 0..3  K-group
    const int wn = (warp >> 1) & 1;  // 0..1  N-half
    const int wm = warp & 1;         // 0..1  M-half
    const int col0 = blockIdx.x * CPB;
    const int lrow = ((lane >> 3) & 1) * 8 + (lane & 7);
    const int lcol = (lane >> 4) * 8;
    const int x2row = lane & 15;

    const __nv_bfloat16* W0h = g_W0i + (size_t)EMB * 6000;

    // -------- load persistent W0h block columns into smem (stride WPS) --------
    {
        for (int slot = tid; slot < 36 * 6; slot += 512) {
            const int row = 1500 + slot / 6, v = slot % 6;
            *reinterpret_cast<uint4*>(&S->Wp[row][v * 8]) = make_uint4(0u, 0u, 0u, 0u);
        }
        for (int idx = tid; idx < 1500 * 6; idx += 512) {
            const int row = idx / 6, v = idx % 6;
            uint32_t d = (uint32_t)__cvta_generic_to_shared(&S->Wp[row][v * 8]);
            const void* s = W0h + (size_t)row * 6000 + col0 + v * 8;
            asm volatile("cp.async.cg.shared.global [%0], [%1], 16;" :: "r"(d), "l"(s));
        }
        asm volatile("cp.async.commit_group;");
        asm volatile("cp.async.wait_group 0;");
    }

    // -------- bootstrap: gates0(0) from xz0(0)+b0 (h(-1)=0, c=0) --------
#pragma unroll
    for (int i = 0; i < 2; i++) {
        const int ul = i * 512 + tid;
        if (ul < 768) {
            const int bb = ul / 12;
            const int u  = ul % 12;
            const int gc = col0 + 4 * u;
            const float4 xz = *reinterpret_cast<const float4*>(&g_xz0[(size_t)bb * 6000 + gc]);
            const float4 b4v = *reinterpret_cast<const float4*>(&g_b0i[gc]);
            const float zi = xz.x + b4v.x, zj = xz.y + b4v.y;
            const float zo = xz.w + b4v.w;
            const float cn = sigmoidf_(zi) * tanhf(zj);
            const int ju = blockIdx.x * 12 + u;
            g_c0[bb * HID + ju] = cn;
            g_h0[0][bb * HROW + ju] = __float2bfloat16(tanhf(cn) * sigmoidf_(zo));
        }
    }
    unsigned gen = 1;
    grid_barrier(gen);

    // warp-private loader lane assignments (loop-invariant)
    const int arow_l = wm * 32 + wn * 16 + (lane >> 1);   // A: 16 rows x 2 vec per warp
    const int acv_l  = kg * 16 + (lane & 1) * 8;
    const int brow_l = kg * 16 + wm * 8 + lane / 3;       // B: 8 rows x 3 vec (lane<24)
    const int bv_l   = wn * 24 + (lane % 3) * 8;

#pragma unroll 1
    for (int t = 0; t < T; t++) {
        const int p = t & 1;
        const __nv_bfloat16* Ah0 = g_h0[p];        // h0(t)
        const __nv_bfloat16* Ah1 = g_h1[1 - p];    // h1(t-1)
        const __nv_bfloat16* W1a = g_W1i;
        const __nv_bfloat16* W1b = g_W1i + (size_t)1500 * 6000;

        auto issue = [&](int it) {
            const bool s1 = (it >= 24);
            const __nv_bfloat16* Ab = s1 ? Ah1 : Ah0;
            const __nv_bfloat16* Wb1 = s1 ? W1b : W1a;
            const int kk = (s1 ? (it - 24) : it) * 64;
            const int sb = it % RC_PIPE;
            {
                uint32_t da = (uint32_t)__cvta_generic_to_shared(&S->As[sb][arow_l][acv_l]);
                const void* sa = Ab + (size_t)arow_l * HROW + kk + acv_l;
                asm volatile("cp.async.cg.shared.global [%0], [%1], 16;" :: "r"(da), "l"(sa));
            }
            if (lane < 24) {
                int krow = kk + brow_l;
                const int bytes = (krow < 1500) ? 16 : 0;
                if (krow >= 1500) krow = 0;
                uint32_t db1 = (uint32_t)__cvta_generic_to_shared(&S->Bs1[sb][brow_l][bv_l]);
                const void* sb1 = Wb1 + (size_t)krow * 6000 + col0 + bv_l;
                asm volatile("cp.async.cg.shared.global [%0], [%1], 16, %2;"
                             :: "r"(db1), "l"(sb1), "r"(bytes));
            }
        };

        float accA[2][3][4], accB[2][3][4];
#pragma unroll
        for (int mt = 0; mt < 2; mt++)
#pragma unroll
            for (int nt = 0; nt < 3; nt++)
#pragma unroll
                for (int r = 0; r < 4; r++) { accA[mt][nt][r] = 0.0f; accB[mt][nt][r] = 0.0f; }

        issue(0);
        asm volatile("cp.async.commit_group;");
        issue(1);
        asm volatile("cp.async.commit_group;");

        const int ks = kg * 16;
        const int barid = 1 + kg;

#define MMA_(ACC, AT, R0, R1)                                                    \
    asm volatile("mma.sync.aligned.m16n8k16.row.col.f32.bf16.bf16.f32 "          \
                 "{%0,%1,%2,%3}, {%4,%5,%6,%7}, {%8,%9}, {%0,%1,%2,%3};"         \
                 : "+f"(ACC[0]), "+f"(ACC[1]), "+f"(ACC[2]), "+f"(ACC[3])        \
                 : "r"(AT[0]), "r"(AT[1]), "r"(AT[2]), "r"(AT[3]), "r"(R0), "r"(R1))

        // ---- segment 1: A=h0(t); accA from persistent Wp, accB from Bs1 ----
#pragma unroll 1
        for (int it = 0; it < 24; it++) {
            asm volatile("cp.async.wait_group 1;");
            asm volatile("bar.sync %0, 128;" :: "r"(barid) : "memory");
            issue(it + 2);
            asm volatile("cp.async.commit_group;");

            const int b = it % RC_PIPE;
            const int kk = it * 64;
            uint32_t a4[2][4];
#pragma unroll
            for (int mt = 0; mt < 2; mt++) {
                uint32_t addr = (uint32_t)__cvta_generic_to_shared(
                    &S->As[b][(wm * 2 + mt) * 16 + lrow][ks + lcol]);
                asm volatile("ldmatrix.sync.aligned.m8n8.x4.shared.b16 {%0,%1,%2,%3}, [%4];"
                    : "=r"(a4[mt][0]), "=r"(a4[mt][1]), "=r"(a4[mt][2]), "=r"(a4[mt][3])
                    : "r"(addr));
            }
            uint32_t b0q[4], b0d[2], b1q[4], b1d[2];
            {
                uint32_t addr = (uint32_t)__cvta_generic_to_shared(
                    &S->Wp[kk + ks + lrow][wn * 24 + lcol]);
                asm volatile("ldmatrix.sync.aligned.m8n8.x4.trans.shared.b16 {%0,%1,%2,%3}, [%4];"
                    : "=r"(b0q[0]), "=r"(b0q[1]), "=r"(b0q[2]), "=r"(b0q[3]) : "r"(addr));
                uint32_t addr2 = (uint32_t)__cvta_generic_to_shared(
                    &S->Wp[kk + ks + x2row][wn * 24 + 16]);
                asm volatile("ldmatrix.sync.aligned.m8n8.x2.trans.shared.b16 {%0,%1}, [%2];"
                    : "=r"(b0d[0]), "=r"(b0d[1]) : "r"(addr2));
            }
            {
                uint32_t addr = (uint32_t)__cvta_generic_to_shared(
                    &S->Bs1[b][ks + lrow][wn * 24 + lcol]);
                asm volatile("ldmatrix.sync.aligned.m8n8.x4.trans.shared.b16 {%0,%1,%2,%3}, [%4];"
                    : "=r"(b1q[0]), "=r"(b1q[1]), "=r"(b1q[2]), "=r"(b1q[3]) : "r"(addr));
                uint32_t addr2 = (uint32_t)__cvta_generic_to_shared(
                    &S->Bs1[b][ks + x2row][wn * 24 + 16]);
                asm volatile("ldmatrix.sync.aligned.m8n8.x2.trans.shared.b16 {%0,%1}, [%2];"
                    : "=r"(b1d[0]), "=r"(b1d[1]) : "r"(addr2));
            }
#pragma unroll
            for (int mt = 0; mt < 2; mt++) {
                MMA_(accA[mt][0], a4[mt], b0q[0], b0q[1]);
                MMA_(accA[mt][1], a4[mt], b0q[2], b0q[3]);
                MMA_(accA[mt][2], a4[mt], b0d[0], b0d[1]);
                MMA_(accB[mt][0], a4[mt], b1q[0], b1q[1]);
                MMA_(accB[mt][1], a4[mt], b1q[2], b1q[3]);
                MMA_(accB[mt][2], a4[mt], b1d[0], b1d[1]);
            }
        }

        // ---- segment 2: A=h1(t-1), Bs1->accB, 24 iters ----
#pragma unroll 1
        for (int it = 24; it < 48; it++) {
            asm volatile("cp.async.wait_group 1;");
            asm volatile("bar.sync %0, 128;" :: "r"(barid) : "memory");
            if (it + 2 < 48) issue(it + 2);
            asm volatile("cp.async.commit_group;");

            const int b = it % RC_PIPE;
            uint32_t a4[2][4];
#pragma unroll
            for (int mt = 0; mt < 2; mt++) {
                uint32_t addr = (uint32_t)__cvta_generic_to_shared(
                    &S->As[b][(wm * 2 + mt) * 16 + lrow][ks + lcol]);
                asm volatile("ldmatrix.sync.aligned.m8n8.x4.shared.b16 {%0,%1,%2,%3}, [%4];"
                    : "=r"(a4[mt][0]), "=r"(a4[mt][1]), "=r"(a4[mt][2]), "=r"(a4[mt][3])
                    : "r"(addr));
            }
            uint32_t b1q[4], b1d[2];
            {
                uint32_t addr = (uint32_t)__cvta_generic_to_shared(
                    &S->Bs1[b][ks + lrow][wn * 24 + lcol]);
                asm volatile("ldmatrix.sync.aligned.m8n8.x4.trans.shared.b16 {%0,%1,%2,%3}, [%4];"
                    : "=r"(b1q[0]), "=r"(b1q[1]), "=r"(b1q[2]), "=r"(b1q[3]) : "r"(addr));
                uint32_t addr2 = (uint32_t)__cvta_generic_to_shared(
                    &S->Bs1[b][ks + x2row][wn * 24 + 16]);
                asm volatile("ldmatrix.sync.aligned.m8n8.x2.trans.shared.b16 {%0,%1}, [%2];"
                    : "=r"(b1d[0]), "=r"(b1d[1]) : "r"(addr2));
            }
#pragma unroll
            for (int mt = 0; mt < 2; mt++) {
                MMA_(accB[mt][0], a4[mt], b1q[0], b1q[1]);
                MMA_(accB[mt][1], a4[mt], b1q[2], b1q[3]);
                MMA_(accB[mt][2], a4[mt], b1d[0], b1d[1]);
            }
        }
#undef MMA_

        // drain all cp.async groups before zsA/zsB alias As
        asm volatile("cp.async.wait_group 0;");

        const int r0m = lane >> 2;
        const int cbm = wn * 24 + (lane & 3) * 2;

        // ---- 2-round merge of accB, then gates1(t) ----
        __syncthreads();
        if (kg == 0 || kg == 2) {
            ZsT zz = (kg == 0) ? zsA : zsB;
#pragma unroll
            for (int mt = 0; mt < 2; mt++) {
                const int rr = (wm * 2 + mt) * 16 + r0m;
#pragma unroll
                for (int nt = 0; nt < 3; nt++) {
                    const int cc = cbm + nt * 8;
                    zz[rr][cc]     = accB[mt][nt][0];
                    zz[rr][cc + 1] = accB[mt][nt][1];
                    zz[rr + 8][cc]     = accB[mt][nt][2];
                    zz[rr + 8][cc + 1] = accB[mt][nt][3];
                }
            }
        }
        __syncthreads();
        if (kg == 1 || kg == 3) {
            ZsT zz = (kg == 1) ? zsA : zsB;
#pragma unroll
            for (int mt = 0; mt < 2; mt++) {
                const int rr = (wm * 2 + mt) * 16 + r0m;
#pragma unroll
                for (int nt = 0; nt < 3; nt++) {
                    const int cc = cbm + nt * 8;
                    zz[rr][cc]     += accB[mt][nt][0];
                    zz[rr][cc + 1] += accB[mt][nt][1];
                    zz[rr + 8][cc]     += accB[mt][nt][2];
                    zz[rr + 8][cc + 1] += accB[mt][nt][3];
                }
            }
        }
        __syncthreads();
#pragma unroll
        for (int i = 0; i < 2; i++) {
            const int ul = i * 512 + tid;
            if (ul < 768) {
                const int bb = ul / 12;
                const int u  = ul % 12;
                const float4 zA = *reinterpret_cast<const float4*>(&zsA[bb][4 * u]);
                const float4 zB = *reinterpret_cast<const float4*>(&zsB[bb][4 * u]);
                const int gc = col0 + 4 * u;
                const float4 b4v = *reinterpret_cast<const float4*>(&g_b1i[gc]);
                const float zi = zA.x + zB.x + b4v.x, zj = zA.y + zB.y + b4v.y;
                const float zf = zA.z + zB.z + b4v.z, zo = zA.w + zB.w + b4v.w;
                const int ju = blockIdx.x * 12 + u;
                const float c = g_c1[bb * HID + ju];
                const float cn = c * sigmoidf_(zf + FORGET_BIAS) + sigmoidf_(zi) * tanhf(zj);
                g_c1[bb * HID + ju] = cn;
                const float h = tanhf(cn) * sigmoidf_(zo);
                const __nv_bfloat16 hb = __float2bfloat16(h);
                g_h1[p][bb * HROW + ju] = hb;
                g_out[(size_t)(t * B + bb) * KA + ju] = hb;
            }
        }

        // ---- 2-round merge of accA, then gates0(t+1) ----
        if (t < T - 1) {
            __syncthreads();
            if (kg == 0 || kg == 2) {
                ZsT zz = (kg == 0) ? zsA : zsB;
#pragma unroll
                for (int mt = 0; mt < 2; mt++) {
                    const int rr = (wm * 2 + mt) * 16 + r0m;
#pragma unroll
                    for (int nt = 0; nt < 3; nt++) {
                        const int cc = cbm + nt * 8;
                        zz[rr][cc]     = accA[mt][nt][0];
                        zz[rr][cc + 1] = accA[mt][nt][1];
                        zz[rr + 8][cc]     = accA[mt][nt][2];
                        zz[rr + 8][cc + 1] = accA[mt][nt][3];
                    }
                }
            }
            __syncthreads();
            if (kg == 1 || kg == 3) {
                ZsT zz = (kg == 1) ? zsA : zsB;
#pragma unroll
                for (int mt = 0; mt < 2; mt++) {
                    const int rr = (wm * 2 + mt) * 16 + r0m;
#pragma unroll
                    for (int nt = 0; nt < 3; nt++) {
                        const int cc = cbm + nt * 8;
                        zz[rr][cc]     += accA[mt][nt][0];
                        zz[rr][cc + 1] += accA[mt][nt][1];
                        zz[rr + 8][cc]     += accA[mt][nt][2];
                        zz[rr + 8][cc + 1] += accA[mt][nt][3];
                    }
                }
            }
            __syncthreads();
#pragma unroll
            for (int i = 0; i < 2; i++) {
                const int ul = i * 512 + tid;
                if (ul < 768) {
                    const int bb = ul / 12;
                    const int u  = ul % 12;
                    const float4 zA = *reinterpret_cast<const float4*>(&zsA[bb][4 * u]);
                    const float4 zB = *reinterpret_cast<const float4*>(&zsB[bb][4 * u]);
                    const int gc = col0 + 4 * u;
                    const float4 b4v = *reinterpret_cast<const float4*>(&g_b0i[gc]);
                    const float4 xz = *reinterpret_cast<const float4*>(
                        &g_xz0[(size_t)((t + 1) * B + bb) * 6000 + gc]);
                    const float zi = zA.x + zB.x + b4v.x + xz.x;
                    const float zj = zA.y + zB.y + b4v.y + xz.y;
                    const float zf = zA.z + zB.z + b4v.z + xz.z;
                    const float zo = zA.w + zB.w + b4v.w + xz.w;
                    const int ju = blockIdx.x * 12 + u;
                    const float c = g_c0[bb * HID + ju];
                    const float cn = c * sigmoidf_(zf + FORGET_BIAS) + sigmoidf_(zi) * tanhf(zj);
                    g_c0[bb * HID + ju] = cn;
                    const float h = tanhf(cn) * sigmoidf_(zo);
                    g_h0[1 - p][bb * HROW + ju] = __float2bfloat16(h);
                }
            }
        }

        gen++;
        grid_barrier(gen);
    }
}

// ---------------- log-softmax + NLL per row ----------------
__global__ void row_nll_kernel(const float* __restrict__ sb, const int* __restrict__ y) {
    __shared__ float red[256];
    const int row = blockIdx.x;
    const float* lr = g_logits + (size_t)row * VOCAB;
    float m = -1e30f;
    for (int v = threadIdx.x; v < VOCAB; v += 256) m = fmaxf(m, lr[v] + sb[v]);
    red[threadIdx.x] = m; __syncthreads();
    for (int s = 128; s > 0; s >>= 1) {
        if (threadIdx.x < s) red[threadIdx.x] = fmaxf(red[threadIdx.x], red[threadIdx.x + s]);
        __syncthreads();
    }
    m = red[0]; __syncthreads();
    float sum = 0.0f;
    for (int v = threadIdx.x; v < VOCAB; v += 256) sum += expf(lr[v] + sb[v] - m);
    red[threadIdx.x] = sum; __syncthreads();
    for (int s = 128; s > 0; s >>= 1) {
        if (threadIdx.x < s) red[threadIdx.x] += red[threadIdx.x + s];
        __syncthreads();
    }
    if (threadIdx.x == 0) {
        const int tgt = y[row];
        g_nll[row] = m + logf(red[0]) - (lr[tgt] + sb[tgt]);
    }
}

__global__ void final_loss_kernel(float* __restrict__ out) {
    __shared__ float red[256];
    float s = 0.0f;
    for (int i = threadIdx.x; i < T * B; i += 256) s += g_nll[i];
    red[threadIdx.x] = s; __syncthreads();
    for (int st = 128; st > 0; st >>= 1) {
        if (threadIdx.x < st) red[threadIdx.x] += red[threadIdx.x + st];
        __syncthreads();
    }
    if (threadIdx.x == 0) out[0] = red[0] / (float)B;
}

// ---------------- launch ----------------
extern "C" void kernel_launch(void* const* d_in, const int* in_sizes, int n_in,
                              void* d_out, int out_size) {
    const int*   x   = (const int*)d_in[0];
    const int*   y   = (const int*)d_in[1];
    const float* emb = (const float*)d_in[2];
    const float* W0  = (const float*)d_in[3];
    const float* b0  = (const float*)d_in[4];
    const float* W1  = (const float*)d_in[5];
    const float* b1  = (const float*)d_in[6];
    const float* sw  = (const float*)d_in[7];
    const float* sb  = (const float*)d_in[8];
    float* out = (float*)d_out;

    void *pW0i, *pSwb, *pInputs, *pOutB, *pXz0, *pLogits;
    cudaGetSymbolAddress(&pW0i, g_W0i);
    cudaGetSymbolAddress(&pSwb, g_swb);
    cudaGetSymbolAddress(&pInputs, g_inputs);
    cudaGetSymbolAddress(&pOutB, g_out);
    cudaGetSymbolAddress(&pXz0, g_xz0);
    cudaGetSymbolAddress(&pLogits, g_logits);

    static bool attrDone = false;
    if (!attrDone) {
        cudaFuncSetAttribute(gemm_pipe, cudaFuncAttributeMaxDynamicSharedMemorySize, GP_SMEM);
        cudaFuncSetAttribute(recurrence_kernel, cudaFuncAttributeMaxDynamicSharedMemorySize, RC_SMEM);
        attrDone = true;
    }

    // (1) fused prep (misc init + all weight conversions)  (2) embedding
    prep_all_kernel<<<2048, 256>>>(b0, b1, W0, W1, sw);
    embed_kernel<<<T * B, 128>>>(x, emb);

    // (3) prefix: xz0 = inputs @ W0i[0:EMB,:]  M=2240, N=6000, K=1500
    {
        dim3 grid((6000 + 127) / 128, (T * B + 127) / 128, 1);
        gemm_pipe<<<grid, 256, GP_SMEM>>>(
            (const __nv_bfloat16*)pInputs, (const __nv_bfloat16*)pW0i, (float*)pXz0,
            T * B, 6000, EMB, KA, 6000, 6000);
    }

    // (4) full recurrence — 512 threads / 16 warps for latency hiding
    recurrence_kernel<<<NBLK, 512, RC_SMEM>>>();

    // (5) logits = outputs @ softmax_w   M=2240, N=10000, K=1500
    {
        dim3 grid((VOCAB + 127) / 128, (T * B + 127) / 128, 1);
        gemm_pipe<<<grid, 256, GP_SMEM>>>(
            (const __nv_bfloat16*)pOutB, (const __nv_bfloat16*)pSwb, (float*)pLogits,
            T * B, VOCAB, HID, KA, VOCAB, VOCAB);
    }

    // (6,7) per-row log-softmax NLL + deterministic final reduction
    row_nll_kernel<<<T * B, 256>>>(sb, y);
    final_loss_kernel<<<1, 256>>>(out);
}